// round 1
// baseline (speedup 1.0000x reference)
#include <cuda_runtime.h>
#include <math.h>

// Problem constants
#define Bb   8
#define Nn_  1024
#define Cc   1024
#define Hh   16
#define Dd   64
#define Mm   (Bb * Nn_)   // 8192

// Scratch (device globals: allocation-free per harness rules)
__device__ float g_qkv[(size_t)Mm * 3 * Cc];   // [8192, 3072]
__device__ float g_att[(size_t)Mm * Cc];       // [8192, 1024]

// ---------------------------------------------------------------------------
// Tiled SGEMM with fused bias: C[M,N] = A[M,K] @ B[K,N] + bias[N]
// 128x128 block tile, BK=8, 256 threads, 8x8 per-thread micro-tile with
// split-quad (4 + 4 at +64) layout for conflict-free LDS.128.
// ---------------------------------------------------------------------------
__global__ __launch_bounds__(256) void sgemm_bias_kernel(
    const float* __restrict__ A, const float* __restrict__ B,
    const float* __restrict__ bias, float* __restrict__ C,
    int M, int N, int K)
{
    const int BM = 128, BN = 128, BK = 8;
    __shared__ float As[BK][BM];
    __shared__ float Bs[BK][BN];

    int tid  = threadIdx.x;
    int row0 = blockIdx.y * BM;
    int col0 = blockIdx.x * BN;
    int tx   = tid & 15;    // 0..15
    int ty   = tid >> 4;    // 0..15

    float acc[8][8];
#pragma unroll
    for (int i = 0; i < 8; i++)
#pragma unroll
        for (int j = 0; j < 8; j++) acc[i][j] = 0.0f;

    // Global-load assignments
    int arow = tid >> 1;            // 0..127
    int acol = (tid & 1) << 2;      // 0 or 4
    int brow = tid >> 5;            // 0..7
    int bcol = (tid & 31) << 2;     // 0..124

    const float* Ab = A + (size_t)(row0 + arow) * K + acol;
    const float* Bp = B + (size_t)brow * N + col0 + bcol;

    for (int k0 = 0; k0 < K; k0 += BK) {
        float4 a4 = *(const float4*)(Ab + k0);
        As[acol + 0][arow] = a4.x;
        As[acol + 1][arow] = a4.y;
        As[acol + 2][arow] = a4.z;
        As[acol + 3][arow] = a4.w;
        *(float4*)&Bs[brow][bcol] = *(const float4*)(Bp + (size_t)k0 * N);
        __syncthreads();

#pragma unroll
        for (int k = 0; k < BK; k++) {
            float ra[8], rb[8];
            *(float4*)&ra[0] = *(const float4*)&As[k][ty * 4];
            *(float4*)&ra[4] = *(const float4*)&As[k][ty * 4 + 64];
            *(float4*)&rb[0] = *(const float4*)&Bs[k][tx * 4];
            *(float4*)&rb[4] = *(const float4*)&Bs[k][tx * 4 + 64];
#pragma unroll
            for (int i = 0; i < 8; i++)
#pragma unroll
                for (int j = 0; j < 8; j++)
                    acc[i][j] += ra[i] * rb[j];
        }
        __syncthreads();
    }

    // Epilogue: rows ty*4+{0..3} and ty*4+64+{0..3}; cols tx*4 and tx*4+64
    float4 bias_lo = *(const float4*)(bias + col0 + tx * 4);
    float4 bias_hi = *(const float4*)(bias + col0 + tx * 4 + 64);
#pragma unroll
    for (int i = 0; i < 8; i++) {
        int r = row0 + ty * 4 + (i & 3) + ((i >> 2) ? 64 : 0);
        float* crow = C + (size_t)r * N + col0;
        float4 lo, hi;
        lo.x = acc[i][0] + bias_lo.x;
        lo.y = acc[i][1] + bias_lo.y;
        lo.z = acc[i][2] + bias_lo.z;
        lo.w = acc[i][3] + bias_lo.w;
        hi.x = acc[i][4] + bias_hi.x;
        hi.y = acc[i][5] + bias_hi.y;
        hi.z = acc[i][6] + bias_hi.z;
        hi.w = acc[i][7] + bias_hi.w;
        *(float4*)(crow + tx * 4)      = lo;
        *(float4*)(crow + tx * 4 + 64) = hi;
    }
}

// ---------------------------------------------------------------------------
// Flash-attention (fp32): one thread per query row, online softmax.
// grid = (B*H, N/128), block = 128.
// qkv layout per row (stride 3072): [q(16 heads x 64) | k(...) | v(...)]
// Output written as [b, n, h*64 + d] (= [8192, 1024]) ready for proj GEMM.
// ---------------------------------------------------------------------------
__global__ __launch_bounds__(128) void attn_kernel(
    const float* __restrict__ qkv, float* __restrict__ out)
{
    int bh = blockIdx.x;           // 0..127
    int b  = bh >> 4;
    int h  = bh & 15;
    int n  = blockIdx.y * 128 + threadIdx.x;
    const float scale = 0.125f;    // 1/sqrt(64)

    __shared__ float Ks[16][64];
    __shared__ float Vs[16][64];

    // Load this thread's q row into registers
    const float* qrow = qkv + ((size_t)(b * Nn_ + n)) * 3072 + h * 64;
    float q[64];
#pragma unroll
    for (int d = 0; d < 64; d += 4) {
        float4 v = *(const float4*)(qrow + d);
        q[d] = v.x; q[d + 1] = v.y; q[d + 2] = v.z; q[d + 3] = v.w;
    }

    float o[64];
#pragma unroll
    for (int d = 0; d < 64; d++) o[d] = 0.0f;
    float m = -1e30f, l = 0.0f;

    int t  = threadIdx.x;
    int lr = t >> 4;            // 0..7
    int lc = (t & 15) << 2;     // 0..60

    const float* kbase = qkv + ((size_t)(b * Nn_)) * 3072 + 1024 + h * 64;
    const float* vbase = kbase + 1024;

    for (int j0 = 0; j0 < Nn_; j0 += 16) {
        __syncthreads();   // previous tile fully consumed
#pragma unroll
        for (int rr = 0; rr < 16; rr += 8) {
            int r = rr + lr;
            *(float4*)&Ks[r][lc] = *(const float4*)(kbase + (size_t)(j0 + r) * 3072 + lc);
            *(float4*)&Vs[r][lc] = *(const float4*)(vbase + (size_t)(j0 + r) * 3072 + lc);
        }
        __syncthreads();

        float s[16];
#pragma unroll
        for (int j = 0; j < 16; j++) {
            float acc = 0.0f;
#pragma unroll
            for (int d = 0; d < 64; d++) acc += q[d] * Ks[j][d];
            s[j] = acc * scale;
        }

        float mt = m;
#pragma unroll
        for (int j = 0; j < 16; j++) mt = fmaxf(mt, s[j]);
        float f = __expf(m - mt);
        m = mt;
        l *= f;
#pragma unroll
        for (int d = 0; d < 64; d++) o[d] *= f;

#pragma unroll
        for (int j = 0; j < 16; j++) {
            float p = __expf(s[j] - m);
            l += p;
#pragma unroll
            for (int d = 0; d < 64; d++) o[d] += p * Vs[j][d];
        }
    }

    float inv = 1.0f / l;
    float* orow = out + ((size_t)(b * Nn_ + n)) * Cc + h * 64;
#pragma unroll
    for (int d = 0; d < 64; d += 4) {
        float4 v;
        v.x = o[d] * inv; v.y = o[d + 1] * inv;
        v.z = o[d + 2] * inv; v.w = o[d + 3] * inv;
        *(float4*)(orow + d) = v;
    }
}

// ---------------------------------------------------------------------------
// kernel_launch
// Inputs (metadata order): x, w_qkv, b_qkv, w_proj, b_proj. Output fp32.
// ---------------------------------------------------------------------------
extern "C" void kernel_launch(void* const* d_in, const int* in_sizes, int n_in,
                              void* d_out, int out_size)
{
    const float* x      = (const float*)d_in[0];
    const float* w_qkv  = (const float*)d_in[1];
    const float* b_qkv  = (const float*)d_in[2];
    const float* w_proj = (const float*)d_in[3];
    const float* b_proj = (const float*)d_in[4];
    float* out = (float*)d_out;

    float* qkv = nullptr;
    float* att = nullptr;
    cudaGetSymbolAddress((void**)&qkv, g_qkv);
    cudaGetSymbolAddress((void**)&att, g_att);

    // 1) QKV GEMM: [8192,1024] @ [1024,3072] + b_qkv -> g_qkv
    {
        dim3 grid(3 * Cc / 128, Mm / 128);   // (24, 64)
        sgemm_bias_kernel<<<grid, 256>>>(x, w_qkv, b_qkv, qkv,
                                         Mm, 3 * Cc, Cc);
    }

    // 2) Flash attention -> g_att [8192, 1024]
    {
        dim3 grid(Bb * Hh, Nn_ / 128);       // (128, 8)
        attn_kernel<<<grid, 128>>>(qkv, att);
    }

    // 3) Projection GEMM: [8192,1024] @ [1024,1024] + b_proj -> out
    {
        dim3 grid(Cc / 128, Mm / 128);       // (8, 64)
        sgemm_bias_kernel<<<grid, 256>>>(att, w_proj, b_proj, out,
                                         Mm, Cc, Cc);
    }
}

// round 3
// speedup vs baseline: 1.4410x; 1.4410x over previous
#include <cuda_runtime.h>
#include <cuda_bf16.h>
#include <cstdint>

#define Bb   8
#define Nn_  1024
#define Cc   1024
#define Hh   16
#define Mm   (Bb * Nn_)   // 8192
#define KK   1024

// ---------------------------------------------------------------------------
// Device scratch (allocation-free per harness rules)
// ---------------------------------------------------------------------------
__device__ __align__(256) float         g_qkv[(size_t)Mm * 3 * Cc];     // [8192,3072]
__device__ __align__(256) __nv_bfloat16 g_x_hi[(size_t)Mm * Cc];
__device__ __align__(256) __nv_bfloat16 g_x_lo[(size_t)Mm * Cc];
__device__ __align__(256) __nv_bfloat16 g_att_hi[(size_t)Mm * Cc];
__device__ __align__(256) __nv_bfloat16 g_att_lo[(size_t)Mm * Cc];
__device__ __align__(256) __nv_bfloat16 g_wqkv_hi[(size_t)3 * Cc * Cc]; // [3072,1024] transposed
__device__ __align__(256) __nv_bfloat16 g_wqkv_lo[(size_t)3 * Cc * Cc];
__device__ __align__(256) __nv_bfloat16 g_wproj_hi[(size_t)Cc * Cc];    // [1024,1024] transposed
__device__ __align__(256) __nv_bfloat16 g_wproj_lo[(size_t)Cc * Cc];

// ---------------------------------------------------------------------------
// helpers
// ---------------------------------------------------------------------------
__device__ __forceinline__ uint32_t smem_u32(const void* p) {
    uint32_t a;
    asm("{ .reg .u64 t; cvta.to.shared.u64 t, %1; cvt.u32.u64 %0, t; }" : "=r"(a) : "l"(p));
    return a;
}

__device__ __forceinline__ void mma_bf16(float* d, const uint32_t* a,
                                         uint32_t b0, uint32_t b1) {
    asm volatile(
        "mma.sync.aligned.m16n8k16.row.col.f32.bf16.bf16.f32 "
        "{%0,%1,%2,%3}, {%4,%5,%6,%7}, {%8,%9}, {%0,%1,%2,%3};"
        : "+f"(d[0]), "+f"(d[1]), "+f"(d[2]), "+f"(d[3])
        : "r"(a[0]), "r"(a[1]), "r"(a[2]), "r"(a[3]), "r"(b0), "r"(b1));
}

#define LDSM4(r0, r1, r2, r3, addr)                                          \
    asm volatile("ldmatrix.sync.aligned.m8n8.x4.shared.b16 {%0,%1,%2,%3}, [%4];" \
                 : "=r"(r0), "=r"(r1), "=r"(r2), "=r"(r3) : "r"(addr))

// smem tile layout: 128 rows x 4 segs(16B), row stride 64B, seg ^= (row>>1)&3
__device__ __forceinline__ uint32_t swz(int row, int seg) {
    return (uint32_t)((row << 6) + ((seg ^ ((row >> 1) & 3)) << 4));
}
// ldmatrix lane address for A m16k16 frag (frags: r0-7/k0-7, r8-15/k0-7, r0-7/k8-15, r8-15/k8-15)
__device__ __forceinline__ uint32_t ldsm_a_addr(uint32_t base, int row_base, int ks, int lane) {
    int f = lane >> 3, w = lane & 7;
    int row = row_base + w + ((f & 1) << 3);
    int seg = (ks << 1) + (f >> 1);
    return base + swz(row, seg);
}
// ldmatrix lane address for B: two n8k16 frags (n rows nb..nb+7 then nb+8..nb+15)
__device__ __forceinline__ uint32_t ldsm_b_addr(uint32_t base, int nb, int ks, int lane) {
    int f = lane >> 3, w = lane & 7;
    int row = nb + w + ((f >> 1) << 3);
    int seg = (ks << 1) + (f & 1);
    return base + swz(row, seg);
}

// ---------------------------------------------------------------------------
// bf16 split-precision tensor-core GEMM:
// C[M,Ntot] = (Ah+Al)[M,K] @ (Bh+Bl)[Ntot,K]^T + bias,  K = 1024
// 128x128 CTA tile, BK=32, 256 threads, cp.async double-buffered.
// ---------------------------------------------------------------------------
#define STAGE_BYTES 32768
#define SMEM_BYTES  (2 * STAGE_BYTES)
#define NCHUNK      (KK / 32)

__device__ __forceinline__ void load_chunk(
    uint32_t stage,
    const __nv_bfloat16* ah, const __nv_bfloat16* al,
    const __nv_bfloat16* bh, const __nv_bfloat16* bl,
    int kc, int tid)
{
    const __nv_bfloat16* bases[4] = {ah, al, bh, bl};
    int koff = kc * 32;
#pragma unroll
    for (int t = 0; t < 4; t++) {
        const __nv_bfloat16* base = bases[t];
        uint32_t sdst = stage + t * 8192;
#pragma unroll
        for (int i = 0; i < 2; i++) {
            int idx = tid + (i << 8);        // 0..511
            int r   = idx >> 2;              // 0..127
            int seg = idx & 3;               // 0..3
            const __nv_bfloat16* src = base + (size_t)r * KK + koff + (seg << 3);
            uint32_t dst = sdst + swz(r, seg);
            asm volatile("cp.async.cg.shared.global [%0], [%1], 16;"
                         :: "r"(dst), "l"(src));
        }
    }
}

__global__ __launch_bounds__(256)
void gemm_mma_kernel(const __nv_bfloat16* __restrict__ Ah, const __nv_bfloat16* __restrict__ Al,
                     const __nv_bfloat16* __restrict__ Bh, const __nv_bfloat16* __restrict__ Bl,
                     const float* __restrict__ bias, float* __restrict__ C, int Ntot)
{
    extern __shared__ char smem[];
    uint32_t sb = smem_u32(smem);

    int tid  = threadIdx.x;
    int lane = tid & 31;
    int wid  = tid >> 5;
    int wm   = wid >> 1;      // 0..3
    int wn   = wid & 1;       // 0..1
    int row0 = blockIdx.y * 128;
    int col0 = blockIdx.x * 128;

    const __nv_bfloat16* ah = Ah + (size_t)row0 * KK;
    const __nv_bfloat16* al = Al + (size_t)row0 * KK;
    const __nv_bfloat16* bh = Bh + (size_t)col0 * KK;
    const __nv_bfloat16* bl = Bl + (size_t)col0 * KK;

    float acc[2][8][4];
#pragma unroll
    for (int mt = 0; mt < 2; mt++)
#pragma unroll
        for (int j = 0; j < 8; j++)
#pragma unroll
            for (int e = 0; e < 4; e++) acc[mt][j][e] = 0.0f;

    load_chunk(sb, ah, al, bh, bl, 0, tid);
    asm volatile("cp.async.commit_group;");

    for (int c = 0; c < NCHUNK; c++) {
        uint32_t stage = sb + (uint32_t)(c & 1) * STAGE_BYTES;
        if (c + 1 < NCHUNK) {
            load_chunk(sb + (uint32_t)((c + 1) & 1) * STAGE_BYTES,
                       ah, al, bh, bl, c + 1, tid);
            asm volatile("cp.async.commit_group;");
            asm volatile("cp.async.wait_group 1;");
        } else {
            asm volatile("cp.async.wait_group 0;");
        }
        __syncthreads();

        uint32_t As  = stage;
        uint32_t Als = stage + 8192;
        uint32_t Bs  = stage + 16384;
        uint32_t Bls = stage + 24576;

#pragma unroll
        for (int ks = 0; ks < 2; ks++) {
            uint32_t a_hi[2][4], a_lo[2][4];
#pragma unroll
            for (int mt = 0; mt < 2; mt++) {
                uint32_t aaddr = ldsm_a_addr(As,  wm * 32 + mt * 16, ks, lane);
                LDSM4(a_hi[mt][0], a_hi[mt][1], a_hi[mt][2], a_hi[mt][3], aaddr);
                uint32_t aladdr = ldsm_a_addr(Als, wm * 32 + mt * 16, ks, lane);
                LDSM4(a_lo[mt][0], a_lo[mt][1], a_lo[mt][2], a_lo[mt][3], aladdr);
            }
#pragma unroll
            for (int ntp = 0; ntp < 4; ntp++) {
                uint32_t b_hi[4], b_lo[4];
                uint32_t baddr = ldsm_b_addr(Bs,  wn * 64 + ntp * 16, ks, lane);
                LDSM4(b_hi[0], b_hi[1], b_hi[2], b_hi[3], baddr);
                uint32_t bladdr = ldsm_b_addr(Bls, wn * 64 + ntp * 16, ks, lane);
                LDSM4(b_lo[0], b_lo[1], b_lo[2], b_lo[3], bladdr);
#pragma unroll
                for (int mt = 0; mt < 2; mt++) {
                    mma_bf16(acc[mt][2 * ntp],     a_hi[mt], b_hi[0], b_hi[1]);
                    mma_bf16(acc[mt][2 * ntp],     a_lo[mt], b_hi[0], b_hi[1]);
                    mma_bf16(acc[mt][2 * ntp],     a_hi[mt], b_lo[0], b_lo[1]);
                    mma_bf16(acc[mt][2 * ntp + 1], a_hi[mt], b_hi[2], b_hi[3]);
                    mma_bf16(acc[mt][2 * ntp + 1], a_lo[mt], b_hi[2], b_hi[3]);
                    mma_bf16(acc[mt][2 * ntp + 1], a_hi[mt], b_lo[2], b_lo[3]);
                }
            }
        }
        __syncthreads();
    }

    // Epilogue: d0,d1 = (row, col..col+1); d2,d3 = (row+8, col..col+1)
#pragma unroll
    for (int mt = 0; mt < 2; mt++) {
#pragma unroll
        for (int j = 0; j < 8; j++) {
            int grow = row0 + wm * 32 + mt * 16 + (lane >> 2);
            int gcol = col0 + wn * 64 + j * 8 + ((lane & 3) << 1);
            float2 bv = *(const float2*)(bias + gcol);
            float2 v0, v1;
            v0.x = acc[mt][j][0] + bv.x;
            v0.y = acc[mt][j][1] + bv.y;
            v1.x = acc[mt][j][2] + bv.x;
            v1.y = acc[mt][j][3] + bv.y;
            *(float2*)(C + (size_t)grow * Ntot + gcol)       = v0;
            *(float2*)(C + (size_t)(grow + 8) * Ntot + gcol) = v1;
        }
    }
}

// ---------------------------------------------------------------------------
// fp32 -> bf16 hi/lo split (elementwise)
// ---------------------------------------------------------------------------
__global__ __launch_bounds__(256) void split_kernel(
    const float* __restrict__ x, __nv_bfloat16* __restrict__ hi,
    __nv_bfloat16* __restrict__ lo, int n)
{
    int i = blockIdx.x * blockDim.x + threadIdx.x;
    if (i * 4 >= n) return;
    float4 v = ((const float4*)x)[i];
    __nv_bfloat16 h0 = __float2bfloat16(v.x);
    __nv_bfloat16 h1 = __float2bfloat16(v.y);
    __nv_bfloat16 h2 = __float2bfloat16(v.z);
    __nv_bfloat16 h3 = __float2bfloat16(v.w);
    __nv_bfloat16 l0 = __float2bfloat16(v.x - __bfloat162float(h0));
    __nv_bfloat16 l1 = __float2bfloat16(v.y - __bfloat162float(h1));
    __nv_bfloat16 l2 = __float2bfloat16(v.z - __bfloat162float(h2));
    __nv_bfloat16 l3 = __float2bfloat16(v.w - __bfloat162float(h3));
    __nv_bfloat162 hp0; hp0.x = h0; hp0.y = h1;
    __nv_bfloat162 hp1; hp1.x = h2; hp1.y = h3;
    __nv_bfloat162 lp0; lp0.x = l0; lp0.y = l1;
    __nv_bfloat162 lp1; lp1.x = l2; lp1.y = l3;
    ((__nv_bfloat162*)hi)[2 * i]     = hp0;
    ((__nv_bfloat162*)hi)[2 * i + 1] = hp1;
    ((__nv_bfloat162*)lo)[2 * i]     = lp0;
    ((__nv_bfloat162*)lo)[2 * i + 1] = lp1;
}

// ---------------------------------------------------------------------------
// W[K,N] fp32 -> transposed bf16 hi/lo [N,K]
// ---------------------------------------------------------------------------
__global__ __launch_bounds__(256) void transpose_split_kernel(
    const float* __restrict__ W, __nv_bfloat16* __restrict__ Th,
    __nv_bfloat16* __restrict__ Tl, int K, int N)
{
    __shared__ float t[32][33];
    int n0 = blockIdx.x * 32, k0 = blockIdx.y * 32;
    int tx = threadIdx.x, ty = threadIdx.y;   // 32 x 8
#pragma unroll
    for (int i = 0; i < 32; i += 8)
        t[ty + i][tx] = W[(size_t)(k0 + ty + i) * N + n0 + tx];
    __syncthreads();
#pragma unroll
    for (int i = 0; i < 32; i += 8) {
        int nn = ty + i;
        float v = t[tx][nn];
        __nv_bfloat16 h = __float2bfloat16(v);
        __nv_bfloat16 l = __float2bfloat16(v - __bfloat162float(h));
        Th[(size_t)(n0 + nn) * K + k0 + tx] = h;
        Tl[(size_t)(n0 + nn) * K + k0 + tx] = l;
    }
}

// ---------------------------------------------------------------------------
// Flash-attention (fp32); epilogue writes bf16 hi/lo for the proj GEMM
// ---------------------------------------------------------------------------
__global__ __launch_bounds__(128) void attn_kernel(
    const float* __restrict__ qkv,
    __nv_bfloat16* __restrict__ att_hi, __nv_bfloat16* __restrict__ att_lo)
{
    int bh = blockIdx.x;
    int b  = bh >> 4;
    int h  = bh & 15;
    int n  = blockIdx.y * 128 + threadIdx.x;
    const float scale = 0.125f;

    __shared__ float Ks[16][64];
    __shared__ float Vs[16][64];

    const float* qrow = qkv + ((size_t)(b * Nn_ + n)) * 3072 + h * 64;
    float q[64];
#pragma unroll
    for (int d = 0; d < 64; d += 4) {
        float4 v = *(const float4*)(qrow + d);
        q[d] = v.x; q[d + 1] = v.y; q[d + 2] = v.z; q[d + 3] = v.w;
    }

    float o[64];
#pragma unroll
    for (int d = 0; d < 64; d++) o[d] = 0.0f;
    float m = -1e30f, l = 0.0f;

    int t  = threadIdx.x;
    int lr = t >> 4;
    int lc = (t & 15) << 2;

    const float* kbase = qkv + ((size_t)(b * Nn_)) * 3072 + 1024 + h * 64;
    const float* vbase = kbase + 1024;

    for (int j0 = 0; j0 < Nn_; j0 += 16) {
        __syncthreads();
#pragma unroll
        for (int rr = 0; rr < 16; rr += 8) {
            int r = rr + lr;
            *(float4*)&Ks[r][lc] = *(const float4*)(kbase + (size_t)(j0 + r) * 3072 + lc);
            *(float4*)&Vs[r][lc] = *(const float4*)(vbase + (size_t)(j0 + r) * 3072 + lc);
        }
        __syncthreads();

        float s[16];
#pragma unroll
        for (int j = 0; j < 16; j++) {
            float acc = 0.0f;
#pragma unroll
            for (int d = 0; d < 64; d++) acc += q[d] * Ks[j][d];
            s[j] = acc * scale;
        }

        float mt = m;
#pragma unroll
        for (int j = 0; j < 16; j++) mt = fmaxf(mt, s[j]);
        float f = __expf(m - mt);
        m = mt;
        l *= f;
#pragma unroll
        for (int d = 0; d < 64; d++) o[d] *= f;

#pragma unroll
        for (int j = 0; j < 16; j++) {
            float p = __expf(s[j] - m);
            l += p;
#pragma unroll
            for (int d = 0; d < 64; d++) o[d] += p * Vs[j][d];
        }
    }

    float inv = 1.0f / l;
    size_t base = ((size_t)(b * Nn_ + n)) * Cc + h * 64;
#pragma unroll
    for (int d = 0; d < 64; d += 2) {
        float v0 = o[d] * inv, v1 = o[d + 1] * inv;
        __nv_bfloat16 h0 = __float2bfloat16(v0);
        __nv_bfloat16 h1 = __float2bfloat16(v1);
        __nv_bfloat16 l0 = __float2bfloat16(v0 - __bfloat162float(h0));
        __nv_bfloat16 l1 = __float2bfloat16(v1 - __bfloat162float(h1));
        __nv_bfloat162 hp; hp.x = h0; hp.y = h1;
        __nv_bfloat162 lp; lp.x = l0; lp.y = l1;
        *(__nv_bfloat162*)(att_hi + base + d) = hp;
        *(__nv_bfloat162*)(att_lo + base + d) = lp;
    }
}

// ---------------------------------------------------------------------------
// kernel_launch
// ---------------------------------------------------------------------------
extern "C" void kernel_launch(void* const* d_in, const int* in_sizes, int n_in,
                              void* d_out, int out_size)
{
    const float* x      = (const float*)d_in[0];
    const float* w_qkv  = (const float*)d_in[1];
    const float* b_qkv  = (const float*)d_in[2];
    const float* w_proj = (const float*)d_in[3];
    const float* b_proj = (const float*)d_in[4];
    float* out = (float*)d_out;

    float *qkv;
    __nv_bfloat16 *xh, *xl, *ath, *atl, *wqh, *wql, *wph, *wpl;
    cudaGetSymbolAddress((void**)&qkv, g_qkv);
    cudaGetSymbolAddress((void**)&xh,  g_x_hi);
    cudaGetSymbolAddress((void**)&xl,  g_x_lo);
    cudaGetSymbolAddress((void**)&ath, g_att_hi);
    cudaGetSymbolAddress((void**)&atl, g_att_lo);
    cudaGetSymbolAddress((void**)&wqh, g_wqkv_hi);
    cudaGetSymbolAddress((void**)&wql, g_wqkv_lo);
    cudaGetSymbolAddress((void**)&wph, g_wproj_hi);
    cudaGetSymbolAddress((void**)&wpl, g_wproj_lo);

    static bool attr_done = false;
    if (!attr_done) {
        cudaFuncSetAttribute(gemm_mma_kernel,
                             cudaFuncAttributeMaxDynamicSharedMemorySize, SMEM_BYTES);
        attr_done = true;
    }

    // 1) split x -> bf16 hi/lo
    {
        int n = Mm * Cc;
        split_kernel<<<(n / 4 + 255) / 256, 256>>>(x, xh, xl, n);
    }
    // 2) transpose+split weights
    transpose_split_kernel<<<dim3(3 * Cc / 32, Cc / 32), dim3(32, 8)>>>(w_qkv, wqh, wql, Cc, 3 * Cc);
    transpose_split_kernel<<<dim3(Cc / 32, Cc / 32), dim3(32, 8)>>>(w_proj, wph, wpl, Cc, Cc);

    // 3) QKV GEMM: [8192,1024] @ [3072,1024]^T + b_qkv -> g_qkv fp32
    gemm_mma_kernel<<<dim3(3 * Cc / 128, Mm / 128), 256, SMEM_BYTES>>>(
        xh, xl, wqh, wql, b_qkv, qkv, 3 * Cc);

    // 4) attention -> bf16 hi/lo [8192,1024]
    attn_kernel<<<dim3(Bb * Hh, Nn_ / 128), 128>>>(qkv, ath, atl);

    // 5) proj GEMM: [8192,1024] @ [1024,1024]^T + b_proj -> out fp32
    gemm_mma_kernel<<<dim3(Cc / 128, Mm / 128), 256, SMEM_BYTES>>>(
        ath, atl, wph, wpl, b_proj, out, Cc);
}

// round 4
// speedup vs baseline: 4.3336x; 3.0074x over previous
#include <cuda_runtime.h>
#include <cuda_bf16.h>
#include <cuda_fp16.h>
#include <cstdint>

#define Bb   8
#define Nn_  1024
#define Cc   1024
#define Hh   16
#define Mm   (Bb * Nn_)   // 8192
#define KK   1024

// q pre-scale: 1/sqrt(64) * log2(e), folded into QKV GEMM epilogue (q cols only)
#define ESCALE 0.18033688011112042f

// ---------------------------------------------------------------------------
// Device scratch
// ---------------------------------------------------------------------------
__device__ __align__(256) __half        g_qkvh[(size_t)Mm * 3 * Cc];    // [8192,3072] fp16
__device__ __align__(256) __nv_bfloat16 g_x_hi[(size_t)Mm * Cc];
__device__ __align__(256) __nv_bfloat16 g_x_lo[(size_t)Mm * Cc];
__device__ __align__(256) __nv_bfloat16 g_att_hi[(size_t)Mm * Cc];
__device__ __align__(256) __nv_bfloat16 g_att_lo[(size_t)Mm * Cc];
__device__ __align__(256) __nv_bfloat16 g_wqkv_hi[(size_t)3 * Cc * Cc];
__device__ __align__(256) __nv_bfloat16 g_wqkv_lo[(size_t)3 * Cc * Cc];
__device__ __align__(256) __nv_bfloat16 g_wproj_hi[(size_t)Cc * Cc];
__device__ __align__(256) __nv_bfloat16 g_wproj_lo[(size_t)Cc * Cc];

// ---------------------------------------------------------------------------
// helpers
// ---------------------------------------------------------------------------
__device__ __forceinline__ uint32_t smem_u32(const void* p) {
    uint32_t a;
    asm("{ .reg .u64 t; cvta.to.shared.u64 t, %1; cvt.u32.u64 %0, t; }" : "=r"(a) : "l"(p));
    return a;
}
__device__ __forceinline__ void mma_bf16(float* d, const uint32_t* a,
                                         uint32_t b0, uint32_t b1) {
    asm volatile(
        "mma.sync.aligned.m16n8k16.row.col.f32.bf16.bf16.f32 "
        "{%0,%1,%2,%3}, {%4,%5,%6,%7}, {%8,%9}, {%0,%1,%2,%3};"
        : "+f"(d[0]), "+f"(d[1]), "+f"(d[2]), "+f"(d[3])
        : "r"(a[0]), "r"(a[1]), "r"(a[2]), "r"(a[3]), "r"(b0), "r"(b1));
}
__device__ __forceinline__ void mma_f16(float* d, const uint32_t* a,
                                        uint32_t b0, uint32_t b1) {
    asm volatile(
        "mma.sync.aligned.m16n8k16.row.col.f32.f16.f16.f32 "
        "{%0,%1,%2,%3}, {%4,%5,%6,%7}, {%8,%9}, {%0,%1,%2,%3};"
        : "+f"(d[0]), "+f"(d[1]), "+f"(d[2]), "+f"(d[3])
        : "r"(a[0]), "r"(a[1]), "r"(a[2]), "r"(a[3]), "r"(b0), "r"(b1));
}
#define LDSM4(r0, r1, r2, r3, addr)                                          \
    asm volatile("ldmatrix.sync.aligned.m8n8.x4.shared.b16 {%0,%1,%2,%3}, [%4];" \
                 : "=r"(r0), "=r"(r1), "=r"(r2), "=r"(r3) : "r"(addr))
#define LDSM4T(r0, r1, r2, r3, addr)                                         \
    asm volatile("ldmatrix.sync.aligned.m8n8.x4.trans.shared.b16 {%0,%1,%2,%3}, [%4];" \
                 : "=r"(r0), "=r"(r1), "=r"(r2), "=r"(r3) : "r"(addr))
__device__ __forceinline__ float ex2f(float x) {
    float r; asm("ex2.approx.f32 %0, %1;" : "=f"(r) : "f"(x)); return r;
}

// ---- 64B-row swizzle (GEMM tiles: 4 segs/row) ----
__device__ __forceinline__ uint32_t swz(int row, int seg) {
    return (uint32_t)((row << 6) + ((seg ^ ((row >> 1) & 3)) << 4));
}
__device__ __forceinline__ uint32_t ldsm_a_addr(uint32_t base, int row_base, int ks, int lane) {
    int f = lane >> 3, w = lane & 7;
    int row = row_base + w + ((f & 1) << 3);
    int seg = (ks << 1) + (f >> 1);
    return base + swz(row, seg);
}
__device__ __forceinline__ uint32_t ldsm_b_addr(uint32_t base, int nb, int ks, int lane) {
    int f = lane >> 3, w = lane & 7;
    int row = nb + w + ((f >> 1) << 3);
    int seg = (ks << 1) + (f & 1);
    return base + swz(row, seg);
}

// ---- 128B-row swizzle (attention tiles: 8 segs/row) ----
__device__ __forceinline__ uint32_t swz128(int row, int seg) {
    return (uint32_t)((row << 7) + ((seg ^ (row & 7)) << 4));
}
__device__ __forceinline__ uint32_t ldsmA_q(uint32_t base, int r0, int kt, int lane) {
    int f = lane >> 3;
    return base + swz128(r0 + (lane & 7) + ((f & 1) << 3), (kt << 1) + (f >> 1));
}
__device__ __forceinline__ uint32_t ldsmB_k(uint32_t base, int nb, int kt, int lane) {
    int f = lane >> 3;
    return base + swz128(nb + (lane & 7) + ((f >> 1) << 3), (kt << 1) + (f & 1));
}
__device__ __forceinline__ uint32_t ldsmBT_v(uint32_t base, int kb, int ndb, int lane) {
    int f = lane >> 3;
    return base + swz128(kb + (lane & 7) + ((f & 1) << 3), (ndb << 1) + (f >> 1));
}

// ---------------------------------------------------------------------------
// bf16 split-precision tensor-core GEMM (as R3), templated epilogue:
// HALF_OUT=0: fp32 C + bias.  HALF_OUT=1: fp16 C + bias, cols < scale_cols
// multiplied by ESCALE (q-scaling for attention).
// ---------------------------------------------------------------------------
#define STAGE_BYTES 32768
#define SMEM_BYTES  (2 * STAGE_BYTES)
#define NCHUNK      (KK / 32)

__device__ __forceinline__ void load_chunk(
    uint32_t stage,
    const __nv_bfloat16* ah, const __nv_bfloat16* al,
    const __nv_bfloat16* bh, const __nv_bfloat16* bl,
    int kc, int tid)
{
    const __nv_bfloat16* bases[4] = {ah, al, bh, bl};
    int koff = kc * 32;
#pragma unroll
    for (int t = 0; t < 4; t++) {
        const __nv_bfloat16* base = bases[t];
        uint32_t sdst = stage + t * 8192;
#pragma unroll
        for (int i = 0; i < 2; i++) {
            int idx = tid + (i << 8);
            int r   = idx >> 2;
            int seg = idx & 3;
            const __nv_bfloat16* src = base + (size_t)r * KK + koff + (seg << 3);
            uint32_t dst = sdst + swz(r, seg);
            asm volatile("cp.async.cg.shared.global [%0], [%1], 16;"
                         :: "r"(dst), "l"(src));
        }
    }
}

template <int HALF_OUT>
__global__ __launch_bounds__(256)
void gemm_mma_kernel(const __nv_bfloat16* __restrict__ Ah, const __nv_bfloat16* __restrict__ Al,
                     const __nv_bfloat16* __restrict__ Bh, const __nv_bfloat16* __restrict__ Bl,
                     const float* __restrict__ bias, float* __restrict__ Cf,
                     __half* __restrict__ Ch, int Ntot, int scale_cols)
{
    extern __shared__ char smem[];
    uint32_t sb = smem_u32(smem);

    int tid  = threadIdx.x;
    int lane = tid & 31;
    int wid  = tid >> 5;
    int wm   = wid >> 1;
    int wn   = wid & 1;
    int row0 = blockIdx.y * 128;
    int col0 = blockIdx.x * 128;

    const __nv_bfloat16* ah = Ah + (size_t)row0 * KK;
    const __nv_bfloat16* al = Al + (size_t)row0 * KK;
    const __nv_bfloat16* bh = Bh + (size_t)col0 * KK;
    const __nv_bfloat16* bl = Bl + (size_t)col0 * KK;

    float acc[2][8][4];
#pragma unroll
    for (int mt = 0; mt < 2; mt++)
#pragma unroll
        for (int j = 0; j < 8; j++)
#pragma unroll
            for (int e = 0; e < 4; e++) acc[mt][j][e] = 0.0f;

    load_chunk(sb, ah, al, bh, bl, 0, tid);
    asm volatile("cp.async.commit_group;");

    for (int c = 0; c < NCHUNK; c++) {
        uint32_t stage = sb + (uint32_t)(c & 1) * STAGE_BYTES;
        if (c + 1 < NCHUNK) {
            load_chunk(sb + (uint32_t)((c + 1) & 1) * STAGE_BYTES,
                       ah, al, bh, bl, c + 1, tid);
            asm volatile("cp.async.commit_group;");
            asm volatile("cp.async.wait_group 1;");
        } else {
            asm volatile("cp.async.wait_group 0;");
        }
        __syncthreads();

        uint32_t As  = stage;
        uint32_t Als = stage + 8192;
        uint32_t Bs  = stage + 16384;
        uint32_t Bls = stage + 24576;

#pragma unroll
        for (int ks = 0; ks < 2; ks++) {
            uint32_t a_hi[2][4], a_lo[2][4];
#pragma unroll
            for (int mt = 0; mt < 2; mt++) {
                uint32_t aaddr = ldsm_a_addr(As,  wm * 32 + mt * 16, ks, lane);
                LDSM4(a_hi[mt][0], a_hi[mt][1], a_hi[mt][2], a_hi[mt][3], aaddr);
                uint32_t aladdr = ldsm_a_addr(Als, wm * 32 + mt * 16, ks, lane);
                LDSM4(a_lo[mt][0], a_lo[mt][1], a_lo[mt][2], a_lo[mt][3], aladdr);
            }
#pragma unroll
            for (int ntp = 0; ntp < 4; ntp++) {
                uint32_t b_hi[4], b_lo[4];
                uint32_t baddr = ldsm_b_addr(Bs,  wn * 64 + ntp * 16, ks, lane);
                LDSM4(b_hi[0], b_hi[1], b_hi[2], b_hi[3], baddr);
                uint32_t bladdr = ldsm_b_addr(Bls, wn * 64 + ntp * 16, ks, lane);
                LDSM4(b_lo[0], b_lo[1], b_lo[2], b_lo[3], bladdr);
#pragma unroll
                for (int mt = 0; mt < 2; mt++) {
                    mma_bf16(acc[mt][2 * ntp],     a_hi[mt], b_hi[0], b_hi[1]);
                    mma_bf16(acc[mt][2 * ntp],     a_lo[mt], b_hi[0], b_hi[1]);
                    mma_bf16(acc[mt][2 * ntp],     a_hi[mt], b_lo[0], b_lo[1]);
                    mma_bf16(acc[mt][2 * ntp + 1], a_hi[mt], b_hi[2], b_hi[3]);
                    mma_bf16(acc[mt][2 * ntp + 1], a_lo[mt], b_hi[2], b_hi[3]);
                    mma_bf16(acc[mt][2 * ntp + 1], a_hi[mt], b_lo[2], b_lo[3]);
                }
            }
        }
        __syncthreads();
    }

#pragma unroll
    for (int mt = 0; mt < 2; mt++) {
#pragma unroll
        for (int j = 0; j < 8; j++) {
            int grow = row0 + wm * 32 + mt * 16 + (lane >> 2);
            int gcol = col0 + wn * 64 + j * 8 + ((lane & 3) << 1);
            float2 bv = *(const float2*)(bias + gcol);
            float v0 = acc[mt][j][0] + bv.x;
            float v1 = acc[mt][j][1] + bv.y;
            float v2 = acc[mt][j][2] + bv.x;
            float v3 = acc[mt][j][3] + bv.y;
            if (HALF_OUT) {
                float s = (gcol < scale_cols) ? ESCALE : 1.0f;
                __half2 h0 = __floats2half2_rn(v0 * s, v1 * s);
                __half2 h1 = __floats2half2_rn(v2 * s, v3 * s);
                *(__half2*)(Ch + (size_t)grow * Ntot + gcol)       = h0;
                *(__half2*)(Ch + (size_t)(grow + 8) * Ntot + gcol) = h1;
            } else {
                float2 o0 = make_float2(v0, v1);
                float2 o1 = make_float2(v2, v3);
                *(float2*)(Cf + (size_t)grow * Ntot + gcol)       = o0;
                *(float2*)(Cf + (size_t)(grow + 8) * Ntot + gcol) = o1;
            }
        }
    }
}

// ---------------------------------------------------------------------------
// Tensor-core flash attention (fp16 in, fp32 softmax, bf16 hi/lo out)
// grid = (8 q-tiles, 128 bh), block = 128 (4 warps, 32 q rows each)
// ---------------------------------------------------------------------------
__device__ __forceinline__ void attn_load_kv(
    uint32_t KS, uint32_t VS,
    const __half* kbase, const __half* vbase, int t, int tid)
{
#pragma unroll
    for (int i = 0; i < 2; i++) {
        int idx = tid + (i << 7);       // 0..255
        int r   = idx >> 3;             // 0..31
        int s   = idx & 7;              // 0..7
        size_t goff = (size_t)(t * 32 + r) * 3072 + (s << 3);
        asm volatile("cp.async.cg.shared.global [%0], [%1], 16;"
                     :: "r"(KS + swz128(r, s)), "l"(kbase + goff));
        asm volatile("cp.async.cg.shared.global [%0], [%1], 16;"
                     :: "r"(VS + swz128(r, s)), "l"(vbase + goff));
    }
}

__global__ __launch_bounds__(128)
void attn_mma_kernel(const __half* __restrict__ qkv,
                     __nv_bfloat16* __restrict__ att_hi,
                     __nv_bfloat16* __restrict__ att_lo)
{
    __shared__ __align__(1024) char sm[32768];
    uint32_t sb = smem_u32(sm);
    const uint32_t QS  = sb;
    const uint32_t KS0 = sb + 16384, KS1 = sb + 20480;
    const uint32_t VS0 = sb + 24576, VS1 = sb + 28672;

    int tid  = threadIdx.x;
    int lane = tid & 31;
    int w    = tid >> 5;
    int qt   = blockIdx.x;
    int bh   = blockIdx.y;
    int b    = bh >> 4;
    int h    = bh & 15;

    const __half* qbase = qkv + ((size_t)(b * Nn_ + qt * 128)) * 3072 + h * 64;
    const __half* kbase = qkv + ((size_t)(b * Nn_)) * 3072 + 1024 + h * 64;
    const __half* vbase = kbase + 1024;

    // Q tile (128x64) + KV tile 0 -> group 0
#pragma unroll
    for (int i = 0; i < 8; i++) {
        int idx = tid + (i << 7);
        int r = idx >> 3, s = idx & 7;
        asm volatile("cp.async.cg.shared.global [%0], [%1], 16;"
                     :: "r"(QS + swz128(r, s)), "l"(qbase + (size_t)r * 3072 + (s << 3)));
    }
    attn_load_kv(KS0, VS0, kbase, vbase, 0, tid);
    asm volatile("cp.async.commit_group;");

    float o[2][8][4];
#pragma unroll
    for (int mt = 0; mt < 2; mt++)
#pragma unroll
        for (int nd = 0; nd < 8; nd++)
#pragma unroll
            for (int e = 0; e < 4; e++) o[mt][nd][e] = 0.0f;
    float mrow[2][2] = {{-1e30f, -1e30f}, {-1e30f, -1e30f}};
    float lrow[2][2] = {{0.0f, 0.0f}, {0.0f, 0.0f}};
    uint32_t qf[2][4][4];

    for (int t = 0; t < 32; t++) {
        if (t + 1 < 32) {
            attn_load_kv((t & 1) ? KS0 : KS1, (t & 1) ? VS0 : VS1,
                         kbase, vbase, t + 1, tid);
            asm volatile("cp.async.commit_group;");
            asm volatile("cp.async.wait_group 1;");
        } else {
            asm volatile("cp.async.wait_group 0;");
        }
        __syncthreads();

        if (t == 0) {
#pragma unroll
            for (int mt = 0; mt < 2; mt++)
#pragma unroll
                for (int kt = 0; kt < 4; kt++)
                    LDSM4(qf[mt][kt][0], qf[mt][kt][1], qf[mt][kt][2], qf[mt][kt][3],
                          ldsmA_q(QS, w * 32 + mt * 16, kt, lane));
        }

        uint32_t Kt = (t & 1) ? KS1 : KS0;
        uint32_t Vt = (t & 1) ? VS1 : VS0;

        // S = Q K^T  (128 x 32 per CTA, 32 x 32 per warp)
        float s[2][4][4];
#pragma unroll
        for (int mt = 0; mt < 2; mt++)
#pragma unroll
            for (int j = 0; j < 4; j++)
#pragma unroll
                for (int e = 0; e < 4; e++) s[mt][j][e] = 0.0f;

#pragma unroll
        for (int kt = 0; kt < 4; kt++) {
#pragma unroll
            for (int nb = 0; nb < 2; nb++) {
                uint32_t bk[4];
                LDSM4(bk[0], bk[1], bk[2], bk[3], ldsmB_k(Kt, nb * 16, kt, lane));
#pragma unroll
                for (int mt = 0; mt < 2; mt++) {
                    mma_f16(s[mt][2 * nb],     qf[mt][kt], bk[0], bk[1]);
                    mma_f16(s[mt][2 * nb + 1], qf[mt][kt], bk[2], bk[3]);
                }
            }
        }

        // online softmax (rows: g=lane>>2 and g+8 per mtile)
#pragma unroll
        for (int mt = 0; mt < 2; mt++) {
#pragma unroll
            for (int r = 0; r < 2; r++) {
                float mx = -1e30f;
#pragma unroll
                for (int j = 0; j < 4; j++)
                    mx = fmaxf(mx, fmaxf(s[mt][j][2 * r], s[mt][j][2 * r + 1]));
                mx = fmaxf(mx, __shfl_xor_sync(0xFFFFFFFFu, mx, 1));
                mx = fmaxf(mx, __shfl_xor_sync(0xFFFFFFFFu, mx, 2));
                float mn = fmaxf(mrow[mt][r], mx);
                float f  = ex2f(mrow[mt][r] - mn);
                mrow[mt][r] = mn;
                float ls = 0.0f;
#pragma unroll
                for (int j = 0; j < 4; j++) {
                    float p0 = ex2f(s[mt][j][2 * r]     - mn);
                    float p1 = ex2f(s[mt][j][2 * r + 1] - mn);
                    s[mt][j][2 * r]     = p0;
                    s[mt][j][2 * r + 1] = p1;
                    ls += p0 + p1;
                }
                lrow[mt][r] = lrow[mt][r] * f + ls;
#pragma unroll
                for (int nd = 0; nd < 8; nd++) {
                    o[mt][nd][2 * r]     *= f;
                    o[mt][nd][2 * r + 1] *= f;
                }
            }
        }

        // pack P -> fp16 A-frags; O += P V
        uint32_t pa[2][2][4];
#pragma unroll
        for (int mt = 0; mt < 2; mt++)
#pragma unroll
            for (int kt = 0; kt < 2; kt++) {
                int j0 = 2 * kt, j1 = 2 * kt + 1;
                __half2 h0 = __floats2half2_rn(s[mt][j0][0], s[mt][j0][1]);
                __half2 h1 = __floats2half2_rn(s[mt][j0][2], s[mt][j0][3]);
                __half2 h2 = __floats2half2_rn(s[mt][j1][0], s[mt][j1][1]);
                __half2 h3 = __floats2half2_rn(s[mt][j1][2], s[mt][j1][3]);
                pa[mt][kt][0] = *(uint32_t*)&h0;
                pa[mt][kt][1] = *(uint32_t*)&h1;
                pa[mt][kt][2] = *(uint32_t*)&h2;
                pa[mt][kt][3] = *(uint32_t*)&h3;
            }
#pragma unroll
        for (int kt = 0; kt < 2; kt++) {
#pragma unroll
            for (int ndb = 0; ndb < 4; ndb++) {
                uint32_t bv[4];
                LDSM4T(bv[0], bv[1], bv[2], bv[3], ldsmBT_v(Vt, kt * 16, ndb, lane));
#pragma unroll
                for (int mt = 0; mt < 2; mt++) {
                    mma_f16(o[mt][2 * ndb],     pa[mt][kt], bv[0], bv[1]);
                    mma_f16(o[mt][2 * ndb + 1], pa[mt][kt], bv[2], bv[3]);
                }
            }
        }
        __syncthreads();
    }

    // epilogue
    float inv[2][2];
#pragma unroll
    for (int mt = 0; mt < 2; mt++)
#pragma unroll
        for (int r = 0; r < 2; r++) {
            float lv = lrow[mt][r];
            lv += __shfl_xor_sync(0xFFFFFFFFu, lv, 1);
            lv += __shfl_xor_sync(0xFFFFFFFFu, lv, 2);
            inv[mt][r] = 1.0f / lv;
        }

    int g   = lane >> 2;
    int tig = lane & 3;
#pragma unroll
    for (int mt = 0; mt < 2; mt++) {
        int row = qt * 128 + w * 32 + mt * 16 + g;
        size_t tok0 = ((size_t)(b * Nn_ + row)) * Cc + h * 64;
        size_t tok1 = ((size_t)(b * Nn_ + row + 8)) * Cc + h * 64;
#pragma unroll
        for (int nd = 0; nd < 8; nd++) {
            int col = nd * 8 + tig * 2;
            float v0 = o[mt][nd][0] * inv[mt][0];
            float v1 = o[mt][nd][1] * inv[mt][0];
            float v2 = o[mt][nd][2] * inv[mt][1];
            float v3 = o[mt][nd][3] * inv[mt][1];
            __nv_bfloat16 h0 = __float2bfloat16(v0), h1 = __float2bfloat16(v1);
            __nv_bfloat16 h2 = __float2bfloat16(v2), h3 = __float2bfloat16(v3);
            __nv_bfloat162 hp0; hp0.x = h0; hp0.y = h1;
            __nv_bfloat162 hp1; hp1.x = h2; hp1.y = h3;
            __nv_bfloat162 lp0; lp0.x = __float2bfloat16(v0 - __bfloat162float(h0));
            lp0.y = __float2bfloat16(v1 - __bfloat162float(h1));
            __nv_bfloat162 lp1; lp1.x = __float2bfloat16(v2 - __bfloat162float(h2));
            lp1.y = __float2bfloat16(v3 - __bfloat162float(h3));
            *(__nv_bfloat162*)(att_hi + tok0 + col) = hp0;
            *(__nv_bfloat162*)(att_lo + tok0 + col) = lp0;
            *(__nv_bfloat162*)(att_hi + tok1 + col) = hp1;
            *(__nv_bfloat162*)(att_lo + tok1 + col) = lp1;
        }
    }
}

// ---------------------------------------------------------------------------
// fp32 -> bf16 hi/lo split
// ---------------------------------------------------------------------------
__global__ __launch_bounds__(256) void split_kernel(
    const float* __restrict__ x, __nv_bfloat16* __restrict__ hi,
    __nv_bfloat16* __restrict__ lo, int n)
{
    int i = blockIdx.x * blockDim.x + threadIdx.x;
    if (i * 4 >= n) return;
    float4 v = ((const float4*)x)[i];
    __nv_bfloat16 h0 = __float2bfloat16(v.x);
    __nv_bfloat16 h1 = __float2bfloat16(v.y);
    __nv_bfloat16 h2 = __float2bfloat16(v.z);
    __nv_bfloat16 h3 = __float2bfloat16(v.w);
    __nv_bfloat162 hp0; hp0.x = h0; hp0.y = h1;
    __nv_bfloat162 hp1; hp1.x = h2; hp1.y = h3;
    __nv_bfloat162 lp0; lp0.x = __float2bfloat16(v.x - __bfloat162float(h0));
    lp0.y = __float2bfloat16(v.y - __bfloat162float(h1));
    __nv_bfloat162 lp1; lp1.x = __float2bfloat16(v.z - __bfloat162float(h2));
    lp1.y = __float2bfloat16(v.w - __bfloat162float(h3));
    ((__nv_bfloat162*)hi)[2 * i]     = hp0;
    ((__nv_bfloat162*)hi)[2 * i + 1] = hp1;
    ((__nv_bfloat162*)lo)[2 * i]     = lp0;
    ((__nv_bfloat162*)lo)[2 * i + 1] = lp1;
}

// ---------------------------------------------------------------------------
// W[K,N] fp32 -> transposed bf16 hi/lo [N,K]
// ---------------------------------------------------------------------------
__global__ __launch_bounds__(256) void transpose_split_kernel(
    const float* __restrict__ W, __nv_bfloat16* __restrict__ Th,
    __nv_bfloat16* __restrict__ Tl, int K, int N)
{
    __shared__ float t[32][33];
    int n0 = blockIdx.x * 32, k0 = blockIdx.y * 32;
    int tx = threadIdx.x, ty = threadIdx.y;
#pragma unroll
    for (int i = 0; i < 32; i += 8)
        t[ty + i][tx] = W[(size_t)(k0 + ty + i) * N + n0 + tx];
    __syncthreads();
#pragma unroll
    for (int i = 0; i < 32; i += 8) {
        int nn = ty + i;
        float v = t[tx][nn];
        __nv_bfloat16 h = __float2bfloat16(v);
        __nv_bfloat16 l = __float2bfloat16(v - __bfloat162float(h));
        Th[(size_t)(n0 + nn) * K + k0 + tx] = h;
        Tl[(size_t)(n0 + nn) * K + k0 + tx] = l;
    }
}

// ---------------------------------------------------------------------------
// kernel_launch
// ---------------------------------------------------------------------------
extern "C" void kernel_launch(void* const* d_in, const int* in_sizes, int n_in,
                              void* d_out, int out_size)
{
    const float* x      = (const float*)d_in[0];
    const float* w_qkv  = (const float*)d_in[1];
    const float* b_qkv  = (const float*)d_in[2];
    const float* w_proj = (const float*)d_in[3];
    const float* b_proj = (const float*)d_in[4];
    float* out = (float*)d_out;

    __half* qkvh;
    __nv_bfloat16 *xh, *xl, *ath, *atl, *wqh, *wql, *wph, *wpl;
    cudaGetSymbolAddress((void**)&qkvh, g_qkvh);
    cudaGetSymbolAddress((void**)&xh,  g_x_hi);
    cudaGetSymbolAddress((void**)&xl,  g_x_lo);
    cudaGetSymbolAddress((void**)&ath, g_att_hi);
    cudaGetSymbolAddress((void**)&atl, g_att_lo);
    cudaGetSymbolAddress((void**)&wqh, g_wqkv_hi);
    cudaGetSymbolAddress((void**)&wql, g_wqkv_lo);
    cudaGetSymbolAddress((void**)&wph, g_wproj_hi);
    cudaGetSymbolAddress((void**)&wpl, g_wproj_lo);

    static bool attr_done = false;
    if (!attr_done) {
        cudaFuncSetAttribute(gemm_mma_kernel<0>,
                             cudaFuncAttributeMaxDynamicSharedMemorySize, SMEM_BYTES);
        cudaFuncSetAttribute(gemm_mma_kernel<1>,
                             cudaFuncAttributeMaxDynamicSharedMemorySize, SMEM_BYTES);
        attr_done = true;
    }

    // 1) split x -> bf16 hi/lo
    {
        int n = Mm * Cc;
        split_kernel<<<(n / 4 + 255) / 256, 256>>>(x, xh, xl, n);
    }
    // 2) transpose+split weights
    transpose_split_kernel<<<dim3(3 * Cc / 32, Cc / 32), dim3(32, 8)>>>(w_qkv, wqh, wql, Cc, 3 * Cc);
    transpose_split_kernel<<<dim3(Cc / 32, Cc / 32), dim3(32, 8)>>>(w_proj, wph, wpl, Cc, Cc);

    // 3) QKV GEMM -> fp16 qkv (q columns pre-scaled by 0.125*log2e)
    gemm_mma_kernel<1><<<dim3(3 * Cc / 128, Mm / 128), 256, SMEM_BYTES>>>(
        xh, xl, wqh, wql, b_qkv, nullptr, qkvh, 3 * Cc, Cc);

    // 4) tensor-core flash attention -> bf16 hi/lo
    attn_mma_kernel<<<dim3(Nn_ / 128, Bb * Hh), 128>>>(qkvh, ath, atl);

    // 5) proj GEMM -> fp32 out
    gemm_mma_kernel<0><<<dim3(Cc / 128, Mm / 128), 256, SMEM_BYTES>>>(
        ath, atl, wph, wpl, b_proj, out, nullptr, Cc, 0);
}

// round 5
// speedup vs baseline: 7.9160x; 1.8266x over previous
#include <cuda_runtime.h>
#include <cuda_fp16.h>
#include <cstdint>

#define Bb   8
#define Nn_  1024
#define Cc   1024
#define Hh   16
#define Mm   (Bb * Nn_)   // 8192
#define KK   1024

// q pre-scale: 1/sqrt(64) * log2(e), folded into QKV GEMM epilogue (q cols only)
#define ESCALE 0.18033688011112042f

// ---------------------------------------------------------------------------
// Device scratch
// ---------------------------------------------------------------------------
__device__ __align__(256) __half g_qkvh[(size_t)Mm * 3 * Cc];   // [8192,3072]
__device__ __align__(256) __half g_xh[(size_t)Mm * Cc];         // [8192,1024]
__device__ __align__(256) __half g_atth[(size_t)Mm * Cc];       // [8192,1024]
__device__ __align__(256) __half g_wqkvh[(size_t)3 * Cc * Cc];  // [3072,1024] transposed
__device__ __align__(256) __half g_wprojh[(size_t)Cc * Cc];     // [1024,1024] transposed

// ---------------------------------------------------------------------------
// helpers
// ---------------------------------------------------------------------------
__device__ __forceinline__ uint32_t smem_u32(const void* p) {
    uint32_t a;
    asm("{ .reg .u64 t; cvta.to.shared.u64 t, %1; cvt.u32.u64 %0, t; }" : "=r"(a) : "l"(p));
    return a;
}
__device__ __forceinline__ void mma_f16(float* d, const uint32_t* a,
                                        uint32_t b0, uint32_t b1) {
    asm volatile(
        "mma.sync.aligned.m16n8k16.row.col.f32.f16.f16.f32 "
        "{%0,%1,%2,%3}, {%4,%5,%6,%7}, {%8,%9}, {%0,%1,%2,%3};"
        : "+f"(d[0]), "+f"(d[1]), "+f"(d[2]), "+f"(d[3])
        : "r"(a[0]), "r"(a[1]), "r"(a[2]), "r"(a[3]), "r"(b0), "r"(b1));
}
#define LDSM4(r0, r1, r2, r3, addr)                                          \
    asm volatile("ldmatrix.sync.aligned.m8n8.x4.shared.b16 {%0,%1,%2,%3}, [%4];" \
                 : "=r"(r0), "=r"(r1), "=r"(r2), "=r"(r3) : "r"(addr))
#define LDSM4T(r0, r1, r2, r3, addr)                                         \
    asm volatile("ldmatrix.sync.aligned.m8n8.x4.trans.shared.b16 {%0,%1,%2,%3}, [%4];" \
                 : "=r"(r0), "=r"(r1), "=r"(r2), "=r"(r3) : "r"(addr))
__device__ __forceinline__ float ex2f(float x) {
    float r; asm("ex2.approx.f32 %0, %1;" : "=f"(r) : "f"(x)); return r;
}

// ---- 64B-row swizzle (GEMM tiles: 4 segs/row) ----
__device__ __forceinline__ uint32_t swz(int row, int seg) {
    return (uint32_t)((row << 6) + ((seg ^ ((row >> 1) & 3)) << 4));
}
__device__ __forceinline__ uint32_t ldsm_a_addr(uint32_t base, int row_base, int ks, int lane) {
    int f = lane >> 3, w = lane & 7;
    int row = row_base + w + ((f & 1) << 3);
    int seg = (ks << 1) + (f >> 1);
    return base + swz(row, seg);
}
__device__ __forceinline__ uint32_t ldsm_b_addr(uint32_t base, int nb, int ks, int lane) {
    int f = lane >> 3, w = lane & 7;
    int row = nb + w + ((f >> 1) << 3);
    int seg = (ks << 1) + (f & 1);
    return base + swz(row, seg);
}

// ---- 128B-row swizzle (attention tiles: 8 segs/row) ----
__device__ __forceinline__ uint32_t swz128(int row, int seg) {
    return (uint32_t)((row << 7) + ((seg ^ (row & 7)) << 4));
}
__device__ __forceinline__ uint32_t ldsmA_q(uint32_t base, int r0, int kt, int lane) {
    int f = lane >> 3;
    return base + swz128(r0 + (lane & 7) + ((f & 1) << 3), (kt << 1) + (f >> 1));
}
__device__ __forceinline__ uint32_t ldsmB_k(uint32_t base, int nb, int kt, int lane) {
    int f = lane >> 3;
    return base + swz128(nb + (lane & 7) + ((f >> 1) << 3), (kt << 1) + (f & 1));
}
__device__ __forceinline__ uint32_t ldsmBT_v(uint32_t base, int kb, int ndb, int lane) {
    int f = lane >> 3;
    return base + swz128(kb + (lane & 7) + ((f & 1) << 3), (ndb << 1) + (f >> 1));
}

// ---------------------------------------------------------------------------
// fp16 tensor-core GEMM: C[M,Ntot] = A[M,K] @ B[Ntot,K]^T + bias
// 128x128 CTA tile, BK=32, 256 threads, triple-buffered cp.async.
// HALF_OUT=1: fp16 out, cols < scale_cols scaled by ESCALE.
// ---------------------------------------------------------------------------
#define STAGE_BYTES 16384
#define SMEM_BYTES  (3 * STAGE_BYTES)
#define NCHUNK      (KK / 32)

__device__ __forceinline__ void load_chunk(
    uint32_t stage, const __half* a, const __half* b, int kc, int tid)
{
    const __half* bases[2] = {a, b};
    int koff = kc * 32;
#pragma unroll
    for (int t = 0; t < 2; t++) {
        const __half* base = bases[t];
        uint32_t sdst = stage + t * 8192;
#pragma unroll
        for (int i = 0; i < 2; i++) {
            int idx = tid + (i << 8);        // 0..511
            int r   = idx >> 2;              // 0..127
            int seg = idx & 3;               // 0..3
            const __half* src = base + (size_t)r * KK + koff + (seg << 3);
            uint32_t dst = sdst + swz(r, seg);
            asm volatile("cp.async.cg.shared.global [%0], [%1], 16;"
                         :: "r"(dst), "l"(src));
        }
    }
}

template <int HALF_OUT>
__global__ __launch_bounds__(256)
void gemm_f16_kernel(const __half* __restrict__ A, const __half* __restrict__ B,
                     const float* __restrict__ bias, float* __restrict__ Cf,
                     __half* __restrict__ Ch, int Ntot, int scale_cols)
{
    extern __shared__ char smem[];
    uint32_t sb = smem_u32(smem);

    int tid  = threadIdx.x;
    int lane = tid & 31;
    int wid  = tid >> 5;
    int wm   = wid >> 1;     // 0..3
    int wn   = wid & 1;      // 0..1
    int row0 = blockIdx.y * 128;
    int col0 = blockIdx.x * 128;

    const __half* a = A + (size_t)row0 * KK;
    const __half* b = B + (size_t)col0 * KK;

    float acc[2][8][4];
#pragma unroll
    for (int mt = 0; mt < 2; mt++)
#pragma unroll
        for (int j = 0; j < 8; j++)
#pragma unroll
            for (int e = 0; e < 4; e++) acc[mt][j][e] = 0.0f;

    load_chunk(sb, a, b, 0, tid);
    asm volatile("cp.async.commit_group;");
    load_chunk(sb + STAGE_BYTES, a, b, 1, tid);
    asm volatile("cp.async.commit_group;");

    int st = 0;  // stage index of chunk c
    for (int c = 0; c < NCHUNK; c++) {
        if (c + 2 < NCHUNK) {
            int st2 = st + 2; if (st2 >= 3) st2 -= 3;
            load_chunk(sb + (uint32_t)st2 * STAGE_BYTES, a, b, c + 2, tid);
            asm volatile("cp.async.commit_group;");
            asm volatile("cp.async.wait_group 2;");
        } else if (c + 1 < NCHUNK) {
            asm volatile("cp.async.wait_group 1;");
        } else {
            asm volatile("cp.async.wait_group 0;");
        }
        __syncthreads();

        uint32_t As = sb + (uint32_t)st * STAGE_BYTES;
        uint32_t Bs = As + 8192;

#pragma unroll
        for (int ks = 0; ks < 2; ks++) {
            uint32_t af[2][4];
#pragma unroll
            for (int mt = 0; mt < 2; mt++)
                LDSM4(af[mt][0], af[mt][1], af[mt][2], af[mt][3],
                      ldsm_a_addr(As, wm * 32 + mt * 16, ks, lane));
#pragma unroll
            for (int ntp = 0; ntp < 4; ntp++) {
                uint32_t bf[4];
                LDSM4(bf[0], bf[1], bf[2], bf[3],
                      ldsm_b_addr(Bs, wn * 64 + ntp * 16, ks, lane));
#pragma unroll
                for (int mt = 0; mt < 2; mt++) {
                    mma_f16(acc[mt][2 * ntp],     af[mt], bf[0], bf[1]);
                    mma_f16(acc[mt][2 * ntp + 1], af[mt], bf[2], bf[3]);
                }
            }
        }
        __syncthreads();
        if (++st == 3) st = 0;
    }

#pragma unroll
    for (int mt = 0; mt < 2; mt++) {
#pragma unroll
        for (int j = 0; j < 8; j++) {
            int grow = row0 + wm * 32 + mt * 16 + (lane >> 2);
            int gcol = col0 + wn * 64 + j * 8 + ((lane & 3) << 1);
            float2 bv = *(const float2*)(bias + gcol);
            float v0 = acc[mt][j][0] + bv.x;
            float v1 = acc[mt][j][1] + bv.y;
            float v2 = acc[mt][j][2] + bv.x;
            float v3 = acc[mt][j][3] + bv.y;
            if (HALF_OUT) {
                float s = (gcol < scale_cols) ? ESCALE : 1.0f;
                __half2 h0 = __floats2half2_rn(v0 * s, v1 * s);
                __half2 h1 = __floats2half2_rn(v2 * s, v3 * s);
                *(__half2*)(Ch + (size_t)grow * Ntot + gcol)       = h0;
                *(__half2*)(Ch + (size_t)(grow + 8) * Ntot + gcol) = h1;
            } else {
                *(float2*)(Cf + (size_t)grow * Ntot + gcol)       = make_float2(v0, v1);
                *(float2*)(Cf + (size_t)(grow + 8) * Ntot + gcol) = make_float2(v2, v3);
            }
        }
    }
}

// ---------------------------------------------------------------------------
// Tensor-core flash attention (fp16 in, fp32 softmax, fp16 out)
// grid = (8 q-tiles, 128 bh), block = 128 (4 warps, 32 q rows each)
// ---------------------------------------------------------------------------
__device__ __forceinline__ void attn_load_kv(
    uint32_t KS, uint32_t VS,
    const __half* kbase, const __half* vbase, int t, int tid)
{
#pragma unroll
    for (int i = 0; i < 2; i++) {
        int idx = tid + (i << 7);
        int r   = idx >> 3;
        int s   = idx & 7;
        size_t goff = (size_t)(t * 32 + r) * 3072 + (s << 3);
        asm volatile("cp.async.cg.shared.global [%0], [%1], 16;"
                     :: "r"(KS + swz128(r, s)), "l"(kbase + goff));
        asm volatile("cp.async.cg.shared.global [%0], [%1], 16;"
                     :: "r"(VS + swz128(r, s)), "l"(vbase + goff));
    }
}

__global__ __launch_bounds__(128)
void attn_mma_kernel(const __half* __restrict__ qkv, __half* __restrict__ att)
{
    __shared__ __align__(1024) char sm[32768];
    uint32_t sb = smem_u32(sm);
    const uint32_t QS  = sb;
    const uint32_t KS0 = sb + 16384, KS1 = sb + 20480;
    const uint32_t VS0 = sb + 24576, VS1 = sb + 28672;

    int tid  = threadIdx.x;
    int lane = tid & 31;
    int w    = tid >> 5;
    int qt   = blockIdx.x;
    int bh   = blockIdx.y;
    int b    = bh >> 4;
    int h    = bh & 15;

    const __half* qbase = qkv + ((size_t)(b * Nn_ + qt * 128)) * 3072 + h * 64;
    const __half* kbase = qkv + ((size_t)(b * Nn_)) * 3072 + 1024 + h * 64;
    const __half* vbase = kbase + 1024;

#pragma unroll
    for (int i = 0; i < 8; i++) {
        int idx = tid + (i << 7);
        int r = idx >> 3, s = idx & 7;
        asm volatile("cp.async.cg.shared.global [%0], [%1], 16;"
                     :: "r"(QS + swz128(r, s)), "l"(qbase + (size_t)r * 3072 + (s << 3)));
    }
    attn_load_kv(KS0, VS0, kbase, vbase, 0, tid);
    asm volatile("cp.async.commit_group;");

    float o[2][8][4];
#pragma unroll
    for (int mt = 0; mt < 2; mt++)
#pragma unroll
        for (int nd = 0; nd < 8; nd++)
#pragma unroll
            for (int e = 0; e < 4; e++) o[mt][nd][e] = 0.0f;
    float mrow[2][2] = {{-1e30f, -1e30f}, {-1e30f, -1e30f}};
    float lrow[2][2] = {{0.0f, 0.0f}, {0.0f, 0.0f}};
    uint32_t qf[2][4][4];

    for (int t = 0; t < 32; t++) {
        if (t + 1 < 32) {
            attn_load_kv((t & 1) ? KS0 : KS1, (t & 1) ? VS0 : VS1,
                         kbase, vbase, t + 1, tid);
            asm volatile("cp.async.commit_group;");
            asm volatile("cp.async.wait_group 1;");
        } else {
            asm volatile("cp.async.wait_group 0;");
        }
        __syncthreads();

        if (t == 0) {
#pragma unroll
            for (int mt = 0; mt < 2; mt++)
#pragma unroll
                for (int kt = 0; kt < 4; kt++)
                    LDSM4(qf[mt][kt][0], qf[mt][kt][1], qf[mt][kt][2], qf[mt][kt][3],
                          ldsmA_q(QS, w * 32 + mt * 16, kt, lane));
        }

        uint32_t Kt = (t & 1) ? KS1 : KS0;
        uint32_t Vt = (t & 1) ? VS1 : VS0;

        float s[2][4][4];
#pragma unroll
        for (int mt = 0; mt < 2; mt++)
#pragma unroll
            for (int j = 0; j < 4; j++)
#pragma unroll
                for (int e = 0; e < 4; e++) s[mt][j][e] = 0.0f;

#pragma unroll
        for (int kt = 0; kt < 4; kt++) {
#pragma unroll
            for (int nb = 0; nb < 2; nb++) {
                uint32_t bk[4];
                LDSM4(bk[0], bk[1], bk[2], bk[3], ldsmB_k(Kt, nb * 16, kt, lane));
#pragma unroll
                for (int mt = 0; mt < 2; mt++) {
                    mma_f16(s[mt][2 * nb],     qf[mt][kt], bk[0], bk[1]);
                    mma_f16(s[mt][2 * nb + 1], qf[mt][kt], bk[2], bk[3]);
                }
            }
        }

#pragma unroll
        for (int mt = 0; mt < 2; mt++) {
#pragma unroll
            for (int r = 0; r < 2; r++) {
                float mx = -1e30f;
#pragma unroll
                for (int j = 0; j < 4; j++)
                    mx = fmaxf(mx, fmaxf(s[mt][j][2 * r], s[mt][j][2 * r + 1]));
                mx = fmaxf(mx, __shfl_xor_sync(0xFFFFFFFFu, mx, 1));
                mx = fmaxf(mx, __shfl_xor_sync(0xFFFFFFFFu, mx, 2));
                float mn = fmaxf(mrow[mt][r], mx);
                float f  = ex2f(mrow[mt][r] - mn);
                mrow[mt][r] = mn;
                float ls = 0.0f;
#pragma unroll
                for (int j = 0; j < 4; j++) {
                    float p0 = ex2f(s[mt][j][2 * r]     - mn);
                    float p1 = ex2f(s[mt][j][2 * r + 1] - mn);
                    s[mt][j][2 * r]     = p0;
                    s[mt][j][2 * r + 1] = p1;
                    ls += p0 + p1;
                }
                lrow[mt][r] = lrow[mt][r] * f + ls;
#pragma unroll
                for (int nd = 0; nd < 8; nd++) {
                    o[mt][nd][2 * r]     *= f;
                    o[mt][nd][2 * r + 1] *= f;
                }
            }
        }

        uint32_t pa[2][2][4];
#pragma unroll
        for (int mt = 0; mt < 2; mt++)
#pragma unroll
            for (int kt = 0; kt < 2; kt++) {
                int j0 = 2 * kt, j1 = 2 * kt + 1;
                __half2 h0 = __floats2half2_rn(s[mt][j0][0], s[mt][j0][1]);
                __half2 h1 = __floats2half2_rn(s[mt][j0][2], s[mt][j0][3]);
                __half2 h2 = __floats2half2_rn(s[mt][j1][0], s[mt][j1][1]);
                __half2 h3 = __floats2half2_rn(s[mt][j1][2], s[mt][j1][3]);
                pa[mt][kt][0] = *(uint32_t*)&h0;
                pa[mt][kt][1] = *(uint32_t*)&h1;
                pa[mt][kt][2] = *(uint32_t*)&h2;
                pa[mt][kt][3] = *(uint32_t*)&h3;
            }
#pragma unroll
        for (int kt = 0; kt < 2; kt++) {
#pragma unroll
            for (int ndb = 0; ndb < 4; ndb++) {
                uint32_t bv[4];
                LDSM4T(bv[0], bv[1], bv[2], bv[3], ldsmBT_v(Vt, kt * 16, ndb, lane));
#pragma unroll
                for (int mt = 0; mt < 2; mt++) {
                    mma_f16(o[mt][2 * ndb],     pa[mt][kt], bv[0], bv[1]);
                    mma_f16(o[mt][2 * ndb + 1], pa[mt][kt], bv[2], bv[3]);
                }
            }
        }
        __syncthreads();
    }

    float inv[2][2];
#pragma unroll
    for (int mt = 0; mt < 2; mt++)
#pragma unroll
        for (int r = 0; r < 2; r++) {
            float lv = lrow[mt][r];
            lv += __shfl_xor_sync(0xFFFFFFFFu, lv, 1);
            lv += __shfl_xor_sync(0xFFFFFFFFu, lv, 2);
            inv[mt][r] = 1.0f / lv;
        }

    int g   = lane >> 2;
    int tig = lane & 3;
#pragma unroll
    for (int mt = 0; mt < 2; mt++) {
        int row = qt * 128 + w * 32 + mt * 16 + g;
        size_t tok0 = ((size_t)(b * Nn_ + row)) * Cc + h * 64;
        size_t tok1 = ((size_t)(b * Nn_ + row + 8)) * Cc + h * 64;
#pragma unroll
        for (int nd = 0; nd < 8; nd++) {
            int col = nd * 8 + tig * 2;
            __half2 h0 = __floats2half2_rn(o[mt][nd][0] * inv[mt][0],
                                           o[mt][nd][1] * inv[mt][0]);
            __half2 h1 = __floats2half2_rn(o[mt][nd][2] * inv[mt][1],
                                           o[mt][nd][3] * inv[mt][1]);
            *(__half2*)(att + tok0 + col) = h0;
            *(__half2*)(att + tok1 + col) = h1;
        }
    }
}

// ---------------------------------------------------------------------------
// fp32 -> fp16 elementwise
// ---------------------------------------------------------------------------
__global__ __launch_bounds__(256) void convert_half_kernel(
    const float* __restrict__ x, __half* __restrict__ y, int n)
{
    int i = blockIdx.x * blockDim.x + threadIdx.x;
    if (i * 4 >= n) return;
    float4 v = ((const float4*)x)[i];
    __half2 h0 = __floats2half2_rn(v.x, v.y);
    __half2 h1 = __floats2half2_rn(v.z, v.w);
    ((__half2*)y)[2 * i]     = h0;
    ((__half2*)y)[2 * i + 1] = h1;
}

// ---------------------------------------------------------------------------
// W[K,N] fp32 -> transposed fp16 [N,K]
// ---------------------------------------------------------------------------
__global__ __launch_bounds__(256) void transpose_half_kernel(
    const float* __restrict__ W, __half* __restrict__ T, int K, int N)
{
    __shared__ float t[32][33];
    int n0 = blockIdx.x * 32, k0 = blockIdx.y * 32;
    int tx = threadIdx.x, ty = threadIdx.y;   // 32 x 8
#pragma unroll
    for (int i = 0; i < 32; i += 8)
        t[ty + i][tx] = W[(size_t)(k0 + ty + i) * N + n0 + tx];
    __syncthreads();
#pragma unroll
    for (int i = 0; i < 32; i += 8) {
        int nn = ty + i;
        T[(size_t)(n0 + nn) * K + k0 + tx] = __float2half_rn(t[tx][nn]);
    }
}

// ---------------------------------------------------------------------------
// kernel_launch
// ---------------------------------------------------------------------------
extern "C" void kernel_launch(void* const* d_in, const int* in_sizes, int n_in,
                              void* d_out, int out_size)
{
    const float* x      = (const float*)d_in[0];
    const float* w_qkv  = (const float*)d_in[1];
    const float* b_qkv  = (const float*)d_in[2];
    const float* w_proj = (const float*)d_in[3];
    const float* b_proj = (const float*)d_in[4];
    float* out = (float*)d_out;

    __half *qkvh, *xh, *atth, *wqh, *wph;
    cudaGetSymbolAddress((void**)&qkvh, g_qkvh);
    cudaGetSymbolAddress((void**)&xh,   g_xh);
    cudaGetSymbolAddress((void**)&atth, g_atth);
    cudaGetSymbolAddress((void**)&wqh,  g_wqkvh);
    cudaGetSymbolAddress((void**)&wph,  g_wprojh);

    static bool attr_done = false;
    if (!attr_done) {
        cudaFuncSetAttribute(gemm_f16_kernel<0>,
                             cudaFuncAttributeMaxDynamicSharedMemorySize, SMEM_BYTES);
        cudaFuncSetAttribute(gemm_f16_kernel<1>,
                             cudaFuncAttributeMaxDynamicSharedMemorySize, SMEM_BYTES);
        attr_done = true;
    }

    // 1) x -> fp16
    {
        int n = Mm * Cc;
        convert_half_kernel<<<(n / 4 + 255) / 256, 256>>>(x, xh, n);
    }
    // 2) transpose weights -> fp16
    transpose_half_kernel<<<dim3(3 * Cc / 32, Cc / 32), dim3(32, 8)>>>(w_qkv, wqh, Cc, 3 * Cc);
    transpose_half_kernel<<<dim3(Cc / 32, Cc / 32), dim3(32, 8)>>>(w_proj, wph, Cc, Cc);

    // 3) QKV GEMM -> fp16 qkv (q columns pre-scaled by 0.125*log2e)
    gemm_f16_kernel<1><<<dim3(3 * Cc / 128, Mm / 128), 256, SMEM_BYTES>>>(
        xh, wqh, b_qkv, nullptr, qkvh, 3 * Cc, Cc);

    // 4) tensor-core flash attention -> fp16
    attn_mma_kernel<<<dim3(Nn_ / 128, Bb * Hh), 128>>>(qkvh, atth);

    // 5) proj GEMM -> fp32 out
    gemm_f16_kernel<0><<<dim3(Cc / 128, Mm / 128), 256, SMEM_BYTES>>>(
        atth, wph, b_proj, out, nullptr, Cc, 0);
}

// round 6
// speedup vs baseline: 8.6160x; 1.0884x over previous
#include <cuda_runtime.h>
#include <cuda_fp16.h>
#include <cstdint>

#define Bb   8
#define Nn_  1024
#define Cc   1024
#define Hh   16
#define Mm   (Bb * Nn_)   // 8192
#define KK   1024

// q pre-scale: 1/sqrt(64) * log2(e), folded into QKV GEMM epilogue (q cols only)
#define ESCALE 0.18033688011112042f

// ---------------------------------------------------------------------------
// Device scratch
// ---------------------------------------------------------------------------
__device__ __align__(256) __half g_qkvh[(size_t)Mm * 3 * Cc];   // [8192,3072]
__device__ __align__(256) __half g_xh[(size_t)Mm * Cc];         // [8192,1024]
__device__ __align__(256) __half g_atth[(size_t)Mm * Cc];       // [8192,1024]
__device__ __align__(256) __half g_wqkvh[(size_t)3 * Cc * Cc];  // [3072,1024] transposed
__device__ __align__(256) __half g_wprojh[(size_t)Cc * Cc];     // [1024,1024] transposed

// ---------------------------------------------------------------------------
// helpers
// ---------------------------------------------------------------------------
__device__ __forceinline__ uint32_t smem_u32(const void* p) {
    uint32_t a;
    asm("{ .reg .u64 t; cvta.to.shared.u64 t, %1; cvt.u32.u64 %0, t; }" : "=r"(a) : "l"(p));
    return a;
}
__device__ __forceinline__ void mma_f16(float* d, const uint32_t* a,
                                        uint32_t b0, uint32_t b1) {
    asm volatile(
        "mma.sync.aligned.m16n8k16.row.col.f32.f16.f16.f32 "
        "{%0,%1,%2,%3}, {%4,%5,%6,%7}, {%8,%9}, {%0,%1,%2,%3};"
        : "+f"(d[0]), "+f"(d[1]), "+f"(d[2]), "+f"(d[3])
        : "r"(a[0]), "r"(a[1]), "r"(a[2]), "r"(a[3]), "r"(b0), "r"(b1));
}
#define LDSM4(r0, r1, r2, r3, addr)                                          \
    asm volatile("ldmatrix.sync.aligned.m8n8.x4.shared.b16 {%0,%1,%2,%3}, [%4];" \
                 : "=r"(r0), "=r"(r1), "=r"(r2), "=r"(r3) : "r"(addr))
#define LDSM4T(r0, r1, r2, r3, addr)                                         \
    asm volatile("ldmatrix.sync.aligned.m8n8.x4.trans.shared.b16 {%0,%1,%2,%3}, [%4];" \
                 : "=r"(r0), "=r"(r1), "=r"(r2), "=r"(r3) : "r"(addr))
__device__ __forceinline__ float ex2f(float x) {
    float r; asm("ex2.approx.f32 %0, %1;" : "=f"(r) : "f"(x)); return r;
}
__device__ __forceinline__ float rcpf(float x) {
    float r; asm("rcp.approx.f32 %0, %1;" : "=f"(r) : "f"(x)); return r;
}

// ---- 128B-row swizzle (8 x 16B segs per row) ----
__device__ __forceinline__ uint32_t swz128(int row, int seg) {
    return (uint32_t)((row << 7) + ((seg ^ (row & 7)) << 4));
}
// A m16k16 frags from row-major K-major tile (rows x 128B)
__device__ __forceinline__ uint32_t ldsmA_q(uint32_t base, int r0, int kt, int lane) {
    int f = lane >> 3;
    return base + swz128(r0 + (lane & 7) + ((f & 1) << 3), (kt << 1) + (f >> 1));
}
// B two-n8 x k16 frags from row-major (N-major rows) K-major tile
__device__ __forceinline__ uint32_t ldsmB_k(uint32_t base, int nb, int kt, int lane) {
    int f = lane >> 3;
    return base + swz128(nb + (lane & 7) + ((f >> 1) << 3), (kt << 1) + (f & 1));
}
// V^T frags via ldmatrix.trans
__device__ __forceinline__ uint32_t ldsmBT_v(uint32_t base, int kb, int ndb, int lane) {
    int f = lane >> 3;
    return base + swz128(kb + (lane & 7) + ((f & 1) << 3), (ndb << 1) + (f >> 1));
}

// ---------------------------------------------------------------------------
// fp16 tensor-core GEMM: C[M,Ntot] = A[M,K] @ B[Ntot,K]^T + bias
// 128x128 CTA tile, BK=64, 256 threads, 3-stage cp.async pipeline.
// ---------------------------------------------------------------------------
#define STAGE_BYTES 32768          // A(128x64) + B(128x64) fp16
#define SMEM_BYTES  (3 * STAGE_BYTES)
#define NCHUNK      (KK / 64)      // 16

__device__ __forceinline__ void load_chunk64(
    uint32_t stage, const __half* a, const __half* b, int kc, int tid)
{
    int koff = kc * 64;
    const __half* bases[2] = {a, b};
#pragma unroll
    for (int t = 0; t < 2; t++) {
        const __half* base = bases[t];
        uint32_t sdst = stage + t * 16384;
#pragma unroll
        for (int i = 0; i < 4; i++) {
            int idx = tid + (i << 8);        // 0..1023
            int r   = idx >> 3;              // 0..127
            int seg = idx & 7;               // 0..7
            const __half* src = base + (size_t)r * KK + koff + (seg << 3);
            uint32_t dst = sdst + swz128(r, seg);
            asm volatile("cp.async.cg.shared.global [%0], [%1], 16;"
                         :: "r"(dst), "l"(src));
        }
    }
}

template <int HALF_OUT>
__global__ __launch_bounds__(256)
void gemm_f16_kernel(const __half* __restrict__ A, const __half* __restrict__ B,
                     const float* __restrict__ bias, float* __restrict__ Cf,
                     __half* __restrict__ Ch, int Ntot, int scale_cols)
{
    extern __shared__ char smem[];
    uint32_t sb = smem_u32(smem);

    int tid  = threadIdx.x;
    int lane = tid & 31;
    int wid  = tid >> 5;
    int wm   = wid >> 1;     // 0..3
    int wn   = wid & 1;      // 0..1
    int row0 = blockIdx.y * 128;
    int col0 = blockIdx.x * 128;

    const __half* a = A + (size_t)row0 * KK;
    const __half* b = B + (size_t)col0 * KK;

    float acc[2][8][4];
#pragma unroll
    for (int mt = 0; mt < 2; mt++)
#pragma unroll
        for (int j = 0; j < 8; j++)
#pragma unroll
            for (int e = 0; e < 4; e++) acc[mt][j][e] = 0.0f;

    load_chunk64(sb, a, b, 0, tid);
    asm volatile("cp.async.commit_group;");
    load_chunk64(sb + STAGE_BYTES, a, b, 1, tid);
    asm volatile("cp.async.commit_group;");

    int st = 0;
    for (int c = 0; c < NCHUNK; c++) {
        if (c + 2 < NCHUNK) {
            int st2 = st + 2; if (st2 >= 3) st2 -= 3;
            load_chunk64(sb + (uint32_t)st2 * STAGE_BYTES, a, b, c + 2, tid);
            asm volatile("cp.async.commit_group;");
            asm volatile("cp.async.wait_group 2;");
        } else if (c + 1 < NCHUNK) {
            asm volatile("cp.async.wait_group 1;");
        } else {
            asm volatile("cp.async.wait_group 0;");
        }
        __syncthreads();

        uint32_t As = sb + (uint32_t)st * STAGE_BYTES;
        uint32_t Bs = As + 16384;

#pragma unroll
        for (int ks = 0; ks < 4; ks++) {
            uint32_t af[2][4];
#pragma unroll
            for (int mt = 0; mt < 2; mt++)
                LDSM4(af[mt][0], af[mt][1], af[mt][2], af[mt][3],
                      ldsmA_q(As, wm * 32 + mt * 16, ks, lane));
#pragma unroll
            for (int ntp = 0; ntp < 4; ntp++) {
                uint32_t bf[4];
                LDSM4(bf[0], bf[1], bf[2], bf[3],
                      ldsmB_k(Bs, wn * 64 + ntp * 16, ks, lane));
#pragma unroll
                for (int mt = 0; mt < 2; mt++) {
                    mma_f16(acc[mt][2 * ntp],     af[mt], bf[0], bf[1]);
                    mma_f16(acc[mt][2 * ntp + 1], af[mt], bf[2], bf[3]);
                }
            }
        }
        __syncthreads();
        if (++st == 3) st = 0;
    }

#pragma unroll
    for (int mt = 0; mt < 2; mt++) {
#pragma unroll
        for (int j = 0; j < 8; j++) {
            int grow = row0 + wm * 32 + mt * 16 + (lane >> 2);
            int gcol = col0 + wn * 64 + j * 8 + ((lane & 3) << 1);
            float2 bv = *(const float2*)(bias + gcol);
            float v0 = acc[mt][j][0] + bv.x;
            float v1 = acc[mt][j][1] + bv.y;
            float v2 = acc[mt][j][2] + bv.x;
            float v3 = acc[mt][j][3] + bv.y;
            if (HALF_OUT) {
                float s = (gcol < scale_cols) ? ESCALE : 1.0f;
                __half2 h0 = __floats2half2_rn(v0 * s, v1 * s);
                __half2 h1 = __floats2half2_rn(v2 * s, v3 * s);
                *(__half2*)(Ch + (size_t)grow * Ntot + gcol)       = h0;
                *(__half2*)(Ch + (size_t)(grow + 8) * Ntot + gcol) = h1;
            } else {
                *(float2*)(Cf + (size_t)grow * Ntot + gcol)       = make_float2(v0, v1);
                *(float2*)(Cf + (size_t)(grow + 8) * Ntot + gcol) = make_float2(v2, v3);
            }
        }
    }
}

// ---------------------------------------------------------------------------
// Tensor-core flash attention (fp16 in, fp32 softmax, fp16 out)
// grid = (8 q-tiles, 128 bh), block = 128 (4 warps, 32 q rows each)
// KV triple-buffered, conditional rescale.
// ---------------------------------------------------------------------------
__device__ __forceinline__ void attn_load_kv(
    uint32_t KS, uint32_t VS,
    const __half* kbase, const __half* vbase, int t, int tid)
{
#pragma unroll
    for (int i = 0; i < 2; i++) {
        int idx = tid + (i << 7);
        int r   = idx >> 3;
        int s   = idx & 7;
        size_t goff = (size_t)(t * 32 + r) * 3072 + (s << 3);
        asm volatile("cp.async.cg.shared.global [%0], [%1], 16;"
                     :: "r"(KS + swz128(r, s)), "l"(kbase + goff));
        asm volatile("cp.async.cg.shared.global [%0], [%1], 16;"
                     :: "r"(VS + swz128(r, s)), "l"(vbase + goff));
    }
}

__global__ __launch_bounds__(128)
void attn_mma_kernel(const __half* __restrict__ qkv, __half* __restrict__ att)
{
    __shared__ __align__(1024) char sm[40960];
    uint32_t sb = smem_u32(sm);
    const uint32_t QS = sb;                       // 16KB
    uint32_t KS[3] = {sb + 16384, sb + 20480, sb + 24576};
    uint32_t VS[3] = {sb + 28672, sb + 32768, sb + 36864};

    int tid  = threadIdx.x;
    int lane = tid & 31;
    int w    = tid >> 5;
    int qt   = blockIdx.x;
    int bh   = blockIdx.y;
    int b    = bh >> 4;
    int h    = bh & 15;

    const __half* qbase = qkv + ((size_t)(b * Nn_ + qt * 128)) * 3072 + h * 64;
    const __half* kbase = qkv + ((size_t)(b * Nn_)) * 3072 + 1024 + h * 64;
    const __half* vbase = kbase + 1024;

#pragma unroll
    for (int i = 0; i < 8; i++) {
        int idx = tid + (i << 7);
        int r = idx >> 3, s = idx & 7;
        asm volatile("cp.async.cg.shared.global [%0], [%1], 16;"
                     :: "r"(QS + swz128(r, s)), "l"(qbase + (size_t)r * 3072 + (s << 3)));
    }
    attn_load_kv(KS[0], VS[0], kbase, vbase, 0, tid);
    asm volatile("cp.async.commit_group;");
    attn_load_kv(KS[1], VS[1], kbase, vbase, 1, tid);
    asm volatile("cp.async.commit_group;");

    float o[2][8][4];
#pragma unroll
    for (int mt = 0; mt < 2; mt++)
#pragma unroll
        for (int nd = 0; nd < 8; nd++)
#pragma unroll
            for (int e = 0; e < 4; e++) o[mt][nd][e] = 0.0f;
    float mrow[2][2] = {{-1e30f, -1e30f}, {-1e30f, -1e30f}};
    float lrow[2][2] = {{0.0f, 0.0f}, {0.0f, 0.0f}};
    uint32_t qf[2][4][4];

    int st = 0;
    for (int t = 0; t < 32; t++) {
        if (t + 2 < 32) {
            int st2 = st + 2; if (st2 >= 3) st2 -= 3;
            attn_load_kv(KS[st2], VS[st2], kbase, vbase, t + 2, tid);
            asm volatile("cp.async.commit_group;");
            asm volatile("cp.async.wait_group 2;");
        } else if (t + 1 < 32) {
            asm volatile("cp.async.wait_group 1;");
        } else {
            asm volatile("cp.async.wait_group 0;");
        }
        __syncthreads();

        if (t == 0) {
#pragma unroll
            for (int mt = 0; mt < 2; mt++)
#pragma unroll
                for (int kt = 0; kt < 4; kt++)
                    LDSM4(qf[mt][kt][0], qf[mt][kt][1], qf[mt][kt][2], qf[mt][kt][3],
                          ldsmA_q(QS, w * 32 + mt * 16, kt, lane));
        }

        uint32_t Kt = KS[st];
        uint32_t Vt = VS[st];

        float s[2][4][4];
#pragma unroll
        for (int mt = 0; mt < 2; mt++)
#pragma unroll
            for (int j = 0; j < 4; j++)
#pragma unroll
                for (int e = 0; e < 4; e++) s[mt][j][e] = 0.0f;

#pragma unroll
        for (int kt = 0; kt < 4; kt++) {
#pragma unroll
            for (int nb = 0; nb < 2; nb++) {
                uint32_t bk[4];
                LDSM4(bk[0], bk[1], bk[2], bk[3], ldsmB_k(Kt, nb * 16, kt, lane));
#pragma unroll
                for (int mt = 0; mt < 2; mt++) {
                    mma_f16(s[mt][2 * nb],     qf[mt][kt], bk[0], bk[1]);
                    mma_f16(s[mt][2 * nb + 1], qf[mt][kt], bk[2], bk[3]);
                }
            }
        }

#pragma unroll
        for (int mt = 0; mt < 2; mt++) {
#pragma unroll
            for (int r = 0; r < 2; r++) {
                float mx = -1e30f;
#pragma unroll
                for (int j = 0; j < 4; j++)
                    mx = fmaxf(mx, fmaxf(s[mt][j][2 * r], s[mt][j][2 * r + 1]));
                mx = fmaxf(mx, __shfl_xor_sync(0xFFFFFFFFu, mx, 1));
                mx = fmaxf(mx, __shfl_xor_sync(0xFFFFFFFFu, mx, 2));
                float mold = mrow[mt][r];
                if (mx > mold) {                 // rescale only on max update
                    float mn = mx;
                    mrow[mt][r] = mn;
                    float f = ex2f(mold - mn);
                    lrow[mt][r] *= f;
#pragma unroll
                    for (int nd = 0; nd < 8; nd++) {
                        o[mt][nd][2 * r]     *= f;
                        o[mt][nd][2 * r + 1] *= f;
                    }
                }
                float mn = mrow[mt][r];
                float ls = 0.0f;
#pragma unroll
                for (int j = 0; j < 4; j++) {
                    float p0 = ex2f(s[mt][j][2 * r]     - mn);
                    float p1 = ex2f(s[mt][j][2 * r + 1] - mn);
                    s[mt][j][2 * r]     = p0;
                    s[mt][j][2 * r + 1] = p1;
                    ls += p0 + p1;
                }
                lrow[mt][r] += ls;
            }
        }

        uint32_t pa[2][2][4];
#pragma unroll
        for (int mt = 0; mt < 2; mt++)
#pragma unroll
            for (int kt = 0; kt < 2; kt++) {
                int j0 = 2 * kt, j1 = 2 * kt + 1;
                __half2 h0 = __floats2half2_rn(s[mt][j0][0], s[mt][j0][1]);
                __half2 h1 = __floats2half2_rn(s[mt][j0][2], s[mt][j0][3]);
                __half2 h2 = __floats2half2_rn(s[mt][j1][0], s[mt][j1][1]);
                __half2 h3 = __floats2half2_rn(s[mt][j1][2], s[mt][j1][3]);
                pa[mt][kt][0] = *(uint32_t*)&h0;
                pa[mt][kt][1] = *(uint32_t*)&h1;
                pa[mt][kt][2] = *(uint32_t*)&h2;
                pa[mt][kt][3] = *(uint32_t*)&h3;
            }
#pragma unroll
        for (int kt = 0; kt < 2; kt++) {
#pragma unroll
            for (int ndb = 0; ndb < 4; ndb++) {
                uint32_t bv[4];
                LDSM4T(bv[0], bv[1], bv[2], bv[3], ldsmBT_v(Vt, kt * 16, ndb, lane));
#pragma unroll
                for (int mt = 0; mt < 2; mt++) {
                    mma_f16(o[mt][2 * ndb],     pa[mt][kt], bv[0], bv[1]);
                    mma_f16(o[mt][2 * ndb + 1], pa[mt][kt], bv[2], bv[3]);
                }
            }
        }
        __syncthreads();
        if (++st == 3) st = 0;
    }

    float inv[2][2];
#pragma unroll
    for (int mt = 0; mt < 2; mt++)
#pragma unroll
        for (int r = 0; r < 2; r++) {
            float lv = lrow[mt][r];
            lv += __shfl_xor_sync(0xFFFFFFFFu, lv, 1);
            lv += __shfl_xor_sync(0xFFFFFFFFu, lv, 2);
            inv[mt][r] = rcpf(lv);
        }

    int g   = lane >> 2;
    int tig = lane & 3;
#pragma unroll
    for (int mt = 0; mt < 2; mt++) {
        int row = qt * 128 + w * 32 + mt * 16 + g;
        size_t tok0 = ((size_t)(b * Nn_ + row)) * Cc + h * 64;
        size_t tok1 = ((size_t)(b * Nn_ + row + 8)) * Cc + h * 64;
#pragma unroll
        for (int nd = 0; nd < 8; nd++) {
            int col = nd * 8 + tig * 2;
            __half2 h0 = __floats2half2_rn(o[mt][nd][0] * inv[mt][0],
                                           o[mt][nd][1] * inv[mt][0]);
            __half2 h1 = __floats2half2_rn(o[mt][nd][2] * inv[mt][1],
                                           o[mt][nd][3] * inv[mt][1]);
            *(__half2*)(att + tok0 + col) = h0;
            *(__half2*)(att + tok1 + col) = h1;
        }
    }
}

// ---------------------------------------------------------------------------
// fp32 -> fp16 elementwise
// ---------------------------------------------------------------------------
__global__ __launch_bounds__(256) void convert_half_kernel(
    const float* __restrict__ x, __half* __restrict__ y, int n)
{
    int i = blockIdx.x * blockDim.x + threadIdx.x;
    if (i * 4 >= n) return;
    float4 v = ((const float4*)x)[i];
    __half2 h0 = __floats2half2_rn(v.x, v.y);
    __half2 h1 = __floats2half2_rn(v.z, v.w);
    ((__half2*)y)[2 * i]     = h0;
    ((__half2*)y)[2 * i + 1] = h1;
}

// ---------------------------------------------------------------------------
// W[K,N] fp32 -> transposed fp16 [N,K]
// ---------------------------------------------------------------------------
__global__ __launch_bounds__(256) void transpose_half_kernel(
    const float* __restrict__ W, __half* __restrict__ T, int K, int N)
{
    __shared__ float t[32][33];
    int n0 = blockIdx.x * 32, k0 = blockIdx.y * 32;
    int tx = threadIdx.x, ty = threadIdx.y;   // 32 x 8
#pragma unroll
    for (int i = 0; i < 32; i += 8)
        t[ty + i][tx] = W[(size_t)(k0 + ty + i) * N + n0 + tx];
    __syncthreads();
#pragma unroll
    for (int i = 0; i < 32; i += 8) {
        int nn = ty + i;
        T[(size_t)(n0 + nn) * K + k0 + tx] = __float2half_rn(t[tx][nn]);
    }
}

// ---------------------------------------------------------------------------
// kernel_launch
// ---------------------------------------------------------------------------
extern "C" void kernel_launch(void* const* d_in, const int* in_sizes, int n_in,
                              void* d_out, int out_size)
{
    const float* x      = (const float*)d_in[0];
    const float* w_qkv  = (const float*)d_in[1];
    const float* b_qkv  = (const float*)d_in[2];
    const float* w_proj = (const float*)d_in[3];
    const float* b_proj = (const float*)d_in[4];
    float* out = (float*)d_out;

    __half *qkvh, *xh, *atth, *wqh, *wph;
    cudaGetSymbolAddress((void**)&qkvh, g_qkvh);
    cudaGetSymbolAddress((void**)&xh,   g_xh);
    cudaGetSymbolAddress((void**)&atth, g_atth);
    cudaGetSymbolAddress((void**)&wqh,  g_wqkvh);
    cudaGetSymbolAddress((void**)&wph,  g_wprojh);

    static bool attr_done = false;
    if (!attr_done) {
        cudaFuncSetAttribute(gemm_f16_kernel<0>,
                             cudaFuncAttributeMaxDynamicSharedMemorySize, SMEM_BYTES);
        cudaFuncSetAttribute(gemm_f16_kernel<1>,
                             cudaFuncAttributeMaxDynamicSharedMemorySize, SMEM_BYTES);
        attr_done = true;
    }

    // 1) x -> fp16
    {
        int n = Mm * Cc;
        convert_half_kernel<<<(n / 4 + 255) / 256, 256>>>(x, xh, n);
    }
    // 2) transpose weights -> fp16
    transpose_half_kernel<<<dim3(3 * Cc / 32, Cc / 32), dim3(32, 8)>>>(w_qkv, wqh, Cc, 3 * Cc);
    transpose_half_kernel<<<dim3(Cc / 32, Cc / 32), dim3(32, 8)>>>(w_proj, wph, Cc, Cc);

    // 3) QKV GEMM -> fp16 qkv (q columns pre-scaled by 0.125*log2e)
    gemm_f16_kernel<1><<<dim3(3 * Cc / 128, Mm / 128), 256, SMEM_BYTES>>>(
        xh, wqh, b_qkv, nullptr, qkvh, 3 * Cc, Cc);

    // 4) tensor-core flash attention -> fp16
    attn_mma_kernel<<<dim3(Nn_ / 128, Bb * Hh), 128>>>(qkvh, atth);

    // 5) proj GEMM -> fp32 out
    gemm_f16_kernel<0><<<dim3(Cc / 128, Mm / 128), 256, SMEM_BYTES>>>(
        atth, wph, b_proj, out, nullptr, Cc, 0);
}

// round 7
// speedup vs baseline: 8.7289x; 1.0131x over previous
#include <cuda_runtime.h>
#include <cuda_fp16.h>
#include <cstdint>

#define Bb   8
#define Nn_  1024
#define Cc   1024
#define Hh   16
#define Mm   (Bb * Nn_)   // 8192
#define KK   1024

// q pre-scale: 1/sqrt(64) * log2(e), folded into QKV GEMM epilogue (q cols only)
#define ESCALE 0.18033688011112042f

// ---------------------------------------------------------------------------
// Device scratch
// ---------------------------------------------------------------------------
__device__ __align__(256) __half g_qkvh[(size_t)Mm * 3 * Cc];   // [8192,3072]
__device__ __align__(256) __half g_xh[(size_t)Mm * Cc];         // [8192,1024]
__device__ __align__(256) __half g_atth[(size_t)Mm * Cc];       // [8192,1024]
__device__ __align__(256) __half g_wqkvh[(size_t)3 * Cc * Cc];  // [3072,1024] transposed
__device__ __align__(256) __half g_wprojh[(size_t)Cc * Cc];     // [1024,1024] transposed

// ---------------------------------------------------------------------------
// helpers
// ---------------------------------------------------------------------------
__device__ __forceinline__ uint32_t smem_u32(const void* p) {
    uint32_t a;
    asm("{ .reg .u64 t; cvta.to.shared.u64 t, %1; cvt.u32.u64 %0, t; }" : "=r"(a) : "l"(p));
    return a;
}
__device__ __forceinline__ void mma_f16(float* d, const uint32_t* a,
                                        uint32_t b0, uint32_t b1) {
    asm volatile(
        "mma.sync.aligned.m16n8k16.row.col.f32.f16.f16.f32 "
        "{%0,%1,%2,%3}, {%4,%5,%6,%7}, {%8,%9}, {%0,%1,%2,%3};"
        : "+f"(d[0]), "+f"(d[1]), "+f"(d[2]), "+f"(d[3])
        : "r"(a[0]), "r"(a[1]), "r"(a[2]), "r"(a[3]), "r"(b0), "r"(b1));
}
#define LDSM4(r0, r1, r2, r3, addr)                                          \
    asm volatile("ldmatrix.sync.aligned.m8n8.x4.shared.b16 {%0,%1,%2,%3}, [%4];" \
                 : "=r"(r0), "=r"(r1), "=r"(r2), "=r"(r3) : "r"(addr))
#define LDSM4T(r0, r1, r2, r3, addr)                                         \
    asm volatile("ldmatrix.sync.aligned.m8n8.x4.trans.shared.b16 {%0,%1,%2,%3}, [%4];" \
                 : "=r"(r0), "=r"(r1), "=r"(r2), "=r"(r3) : "r"(addr))
__device__ __forceinline__ float ex2f(float x) {
    float r; asm("ex2.approx.f32 %0, %1;" : "=f"(r) : "f"(x)); return r;
}
__device__ __forceinline__ float rcpf(float x) {
    float r; asm("rcp.approx.f32 %0, %1;" : "=f"(r) : "f"(x)); return r;
}

// ---- 128B-row swizzle (8 x 16B segs per row) ----
__device__ __forceinline__ uint32_t swz128(int row, int seg) {
    return (uint32_t)((row << 7) + ((seg ^ (row & 7)) << 4));
}
__device__ __forceinline__ uint32_t ldsmA_q(uint32_t base, int r0, int kt, int lane) {
    int f = lane >> 3;
    return base + swz128(r0 + (lane & 7) + ((f & 1) << 3), (kt << 1) + (f >> 1));
}
__device__ __forceinline__ uint32_t ldsmB_k(uint32_t base, int nb, int kt, int lane) {
    int f = lane >> 3;
    return base + swz128(nb + (lane & 7) + ((f >> 1) << 3), (kt << 1) + (f & 1));
}
__device__ __forceinline__ uint32_t ldsmBT_v(uint32_t base, int kb, int ndb, int lane) {
    int f = lane >> 3;
    return base + swz128(kb + (lane & 7) + ((f & 1) << 3), (ndb << 1) + (f >> 1));
}

// ---------------------------------------------------------------------------
// fp16 tensor-core GEMM: C[M,Ntot] = A[M,K] @ B[Ntot,K]^T + bias
// 128x128 CTA tile, BK=64, 128 threads (4 warps, 64x64 warp tiles),
// 3-stage cp.async pipeline.
// ---------------------------------------------------------------------------
#define STAGE_BYTES 32768          // A(128x64) + B(128x64) fp16
#define SMEM_BYTES  (3 * STAGE_BYTES)
#define NCHUNK      (KK / 64)      // 16

__device__ __forceinline__ void load_chunk64(
    uint32_t stage, const __half* a, const __half* b, int kc, int tid)
{
    int koff = kc * 64;
    const __half* bases[2] = {a, b};
#pragma unroll
    for (int t = 0; t < 2; t++) {
        const __half* base = bases[t];
        uint32_t sdst = stage + t * 16384;
#pragma unroll
        for (int i = 0; i < 8; i++) {
            int idx = tid + (i << 7);        // 0..1023
            int r   = idx >> 3;              // 0..127
            int seg = idx & 7;               // 0..7
            const __half* src = base + (size_t)r * KK + koff + (seg << 3);
            uint32_t dst = sdst + swz128(r, seg);
            asm volatile("cp.async.cg.shared.global [%0], [%1], 16;"
                         :: "r"(dst), "l"(src));
        }
    }
}

template <int HALF_OUT>
__global__ __launch_bounds__(128)
void gemm_f16_kernel(const __half* __restrict__ A, const __half* __restrict__ B,
                     const float* __restrict__ bias, float* __restrict__ Cf,
                     __half* __restrict__ Ch, int Ntot, int scale_cols)
{
    extern __shared__ char smem[];
    uint32_t sb = smem_u32(smem);

    int tid  = threadIdx.x;
    int lane = tid & 31;
    int wid  = tid >> 5;
    int wm   = wid >> 1;     // 0..1
    int wn   = wid & 1;      // 0..1
    int row0 = blockIdx.y * 128;
    int col0 = blockIdx.x * 128;

    const __half* a = A + (size_t)row0 * KK;
    const __half* b = B + (size_t)col0 * KK;

    float acc[4][8][4];
#pragma unroll
    for (int mt = 0; mt < 4; mt++)
#pragma unroll
        for (int j = 0; j < 8; j++)
#pragma unroll
            for (int e = 0; e < 4; e++) acc[mt][j][e] = 0.0f;

    load_chunk64(sb, a, b, 0, tid);
    asm volatile("cp.async.commit_group;");
    load_chunk64(sb + STAGE_BYTES, a, b, 1, tid);
    asm volatile("cp.async.commit_group;");

    int st = 0;
    for (int c = 0; c < NCHUNK; c++) {
        if (c + 2 < NCHUNK) {
            int st2 = st + 2; if (st2 >= 3) st2 -= 3;
            load_chunk64(sb + (uint32_t)st2 * STAGE_BYTES, a, b, c + 2, tid);
            asm volatile("cp.async.commit_group;");
            asm volatile("cp.async.wait_group 2;");
        } else if (c + 1 < NCHUNK) {
            asm volatile("cp.async.wait_group 1;");
        } else {
            asm volatile("cp.async.wait_group 0;");
        }
        __syncthreads();

        uint32_t As = sb + (uint32_t)st * STAGE_BYTES;
        uint32_t Bs = As + 16384;

#pragma unroll
        for (int ks = 0; ks < 4; ks++) {
            uint32_t af[4][4];
#pragma unroll
            for (int mt = 0; mt < 4; mt++)
                LDSM4(af[mt][0], af[mt][1], af[mt][2], af[mt][3],
                      ldsmA_q(As, wm * 64 + mt * 16, ks, lane));
#pragma unroll
            for (int ntp = 0; ntp < 4; ntp++) {
                uint32_t bf[4];
                LDSM4(bf[0], bf[1], bf[2], bf[3],
                      ldsmB_k(Bs, wn * 64 + ntp * 16, ks, lane));
#pragma unroll
                for (int mt = 0; mt < 4; mt++) {
                    mma_f16(acc[mt][2 * ntp],     af[mt], bf[0], bf[1]);
                    mma_f16(acc[mt][2 * ntp + 1], af[mt], bf[2], bf[3]);
                }
            }
        }
        __syncthreads();
        if (++st == 3) st = 0;
    }

#pragma unroll
    for (int mt = 0; mt < 4; mt++) {
#pragma unroll
        for (int j = 0; j < 8; j++) {
            int grow = row0 + wm * 64 + mt * 16 + (lane >> 2);
            int gcol = col0 + wn * 64 + j * 8 + ((lane & 3) << 1);
            float2 bv = *(const float2*)(bias + gcol);
            float v0 = acc[mt][j][0] + bv.x;
            float v1 = acc[mt][j][1] + bv.y;
            float v2 = acc[mt][j][2] + bv.x;
            float v3 = acc[mt][j][3] + bv.y;
            if (HALF_OUT) {
                float s = (gcol < scale_cols) ? ESCALE : 1.0f;
                __half2 h0 = __floats2half2_rn(v0 * s, v1 * s);
                __half2 h1 = __floats2half2_rn(v2 * s, v3 * s);
                *(__half2*)(Ch + (size_t)grow * Ntot + gcol)       = h0;
                *(__half2*)(Ch + (size_t)(grow + 8) * Ntot + gcol) = h1;
            } else {
                *(float2*)(Cf + (size_t)grow * Ntot + gcol)       = make_float2(v0, v1);
                *(float2*)(Cf + (size_t)(grow + 8) * Ntot + gcol) = make_float2(v2, v3);
            }
        }
    }
}

// ---------------------------------------------------------------------------
// Tensor-core flash attention (fp16 in, fp32 softmax, fp16 out)
// grid = (8 q-tiles, 128 bh), block = 256 (8 warps, 16 q rows each)
// KV triple-buffered, conditional rescale.
// ---------------------------------------------------------------------------
__device__ __forceinline__ void attn_load_kv(
    uint32_t KS, uint32_t VS,
    const __half* kbase, const __half* vbase, int t, int tid)
{
    // 256 threads, 32x64 fp16 tile = 256 16B segs each for K and V
    int r = tid >> 3;
    int s = tid & 7;
    size_t goff = (size_t)(t * 32 + r) * 3072 + (s << 3);
    asm volatile("cp.async.cg.shared.global [%0], [%1], 16;"
                 :: "r"(KS + swz128(r, s)), "l"(kbase + goff));
    asm volatile("cp.async.cg.shared.global [%0], [%1], 16;"
                 :: "r"(VS + swz128(r, s)), "l"(vbase + goff));
}

__global__ __launch_bounds__(256)
void attn_mma_kernel(const __half* __restrict__ qkv, __half* __restrict__ att)
{
    __shared__ __align__(1024) char sm[40960];
    uint32_t sb = smem_u32(sm);
    const uint32_t QS = sb;                       // 16KB
    uint32_t KS[3] = {sb + 16384, sb + 20480, sb + 24576};
    uint32_t VS[3] = {sb + 28672, sb + 32768, sb + 36864};

    int tid  = threadIdx.x;
    int lane = tid & 31;
    int w    = tid >> 5;       // 0..7
    int qt   = blockIdx.x;
    int bh   = blockIdx.y;
    int b    = bh >> 4;
    int h    = bh & 15;

    const __half* qbase = qkv + ((size_t)(b * Nn_ + qt * 128)) * 3072 + h * 64;
    const __half* kbase = qkv + ((size_t)(b * Nn_)) * 3072 + 1024 + h * 64;
    const __half* vbase = kbase + 1024;

    // Q tile 128x64 = 1024 segs, 256 threads x 4
#pragma unroll
    for (int i = 0; i < 4; i++) {
        int idx = tid + (i << 8);
        int r = idx >> 3, s = idx & 7;
        asm volatile("cp.async.cg.shared.global [%0], [%1], 16;"
                     :: "r"(QS + swz128(r, s)), "l"(qbase + (size_t)r * 3072 + (s << 3)));
    }
    attn_load_kv(KS[0], VS[0], kbase, vbase, 0, tid);
    asm volatile("cp.async.commit_group;");
    attn_load_kv(KS[1], VS[1], kbase, vbase, 1, tid);
    asm volatile("cp.async.commit_group;");

    float o[8][4];
#pragma unroll
    for (int nd = 0; nd < 8; nd++)
#pragma unroll
        for (int e = 0; e < 4; e++) o[nd][e] = 0.0f;
    float mrow[2] = {-1e30f, -1e30f};
    float lrow[2] = {0.0f, 0.0f};
    uint32_t qf[4][4];

    int st = 0;
    for (int t = 0; t < 32; t++) {
        if (t + 2 < 32) {
            int st2 = st + 2; if (st2 >= 3) st2 -= 3;
            attn_load_kv(KS[st2], VS[st2], kbase, vbase, t + 2, tid);
            asm volatile("cp.async.commit_group;");
            asm volatile("cp.async.wait_group 2;");
        } else if (t + 1 < 32) {
            asm volatile("cp.async.wait_group 1;");
        } else {
            asm volatile("cp.async.wait_group 0;");
        }
        __syncthreads();

        if (t == 0) {
#pragma unroll
            for (int kt = 0; kt < 4; kt++)
                LDSM4(qf[kt][0], qf[kt][1], qf[kt][2], qf[kt][3],
                      ldsmA_q(QS, w * 16, kt, lane));
        }

        uint32_t Kt = KS[st];
        uint32_t Vt = VS[st];

        // S = Q K^T  (16 x 32 per warp)
        float s[4][4];
#pragma unroll
        for (int j = 0; j < 4; j++)
#pragma unroll
            for (int e = 0; e < 4; e++) s[j][e] = 0.0f;

#pragma unroll
        for (int kt = 0; kt < 4; kt++) {
#pragma unroll
            for (int nb = 0; nb < 2; nb++) {
                uint32_t bk[4];
                LDSM4(bk[0], bk[1], bk[2], bk[3], ldsmB_k(Kt, nb * 16, kt, lane));
                mma_f16(s[2 * nb],     qf[kt], bk[0], bk[1]);
                mma_f16(s[2 * nb + 1], qf[kt], bk[2], bk[3]);
            }
        }

        // online softmax (rows g = lane>>2 and g+8)
#pragma unroll
        for (int r = 0; r < 2; r++) {
            float mx = -1e30f;
#pragma unroll
            for (int j = 0; j < 4; j++)
                mx = fmaxf(mx, fmaxf(s[j][2 * r], s[j][2 * r + 1]));
            mx = fmaxf(mx, __shfl_xor_sync(0xFFFFFFFFu, mx, 1));
            mx = fmaxf(mx, __shfl_xor_sync(0xFFFFFFFFu, mx, 2));
            float mold = mrow[r];
            if (mx > mold) {                 // rescale only on max update
                mrow[r] = mx;
                float f = ex2f(mold - mx);
                lrow[r] *= f;
#pragma unroll
                for (int nd = 0; nd < 8; nd++) {
                    o[nd][2 * r]     *= f;
                    o[nd][2 * r + 1] *= f;
                }
            }
            float mn = mrow[r];
            float ls = 0.0f;
#pragma unroll
            for (int j = 0; j < 4; j++) {
                float p0 = ex2f(s[j][2 * r]     - mn);
                float p1 = ex2f(s[j][2 * r + 1] - mn);
                s[j][2 * r]     = p0;
                s[j][2 * r + 1] = p1;
                ls += p0 + p1;
            }
            lrow[r] += ls;
        }

        // pack P -> fp16 A-frags; O += P V
        uint32_t pa[2][4];
#pragma unroll
        for (int kt = 0; kt < 2; kt++) {
            int j0 = 2 * kt, j1 = 2 * kt + 1;
            __half2 h0 = __floats2half2_rn(s[j0][0], s[j0][1]);
            __half2 h1 = __floats2half2_rn(s[j0][2], s[j0][3]);
            __half2 h2 = __floats2half2_rn(s[j1][0], s[j1][1]);
            __half2 h3 = __floats2half2_rn(s[j1][2], s[j1][3]);
            pa[kt][0] = *(uint32_t*)&h0;
            pa[kt][1] = *(uint32_t*)&h1;
            pa[kt][2] = *(uint32_t*)&h2;
            pa[kt][3] = *(uint32_t*)&h3;
        }
#pragma unroll
        for (int kt = 0; kt < 2; kt++) {
#pragma unroll
            for (int ndb = 0; ndb < 4; ndb++) {
                uint32_t bv[4];
                LDSM4T(bv[0], bv[1], bv[2], bv[3], ldsmBT_v(Vt, kt * 16, ndb, lane));
                mma_f16(o[2 * ndb],     pa[kt], bv[0], bv[1]);
                mma_f16(o[2 * ndb + 1], pa[kt], bv[2], bv[3]);
            }
        }
        __syncthreads();
        if (++st == 3) st = 0;
    }

    float inv[2];
#pragma unroll
    for (int r = 0; r < 2; r++) {
        float lv = lrow[r];
        lv += __shfl_xor_sync(0xFFFFFFFFu, lv, 1);
        lv += __shfl_xor_sync(0xFFFFFFFFu, lv, 2);
        inv[r] = rcpf(lv);
    }

    int g   = lane >> 2;
    int tig = lane & 3;
    int row = qt * 128 + w * 16 + g;
    size_t tok0 = ((size_t)(b * Nn_ + row)) * Cc + h * 64;
    size_t tok1 = ((size_t)(b * Nn_ + row + 8)) * Cc + h * 64;
#pragma unroll
    for (int nd = 0; nd < 8; nd++) {
        int col = nd * 8 + tig * 2;
        __half2 h0 = __floats2half2_rn(o[nd][0] * inv[0], o[nd][1] * inv[0]);
        __half2 h1 = __floats2half2_rn(o[nd][2] * inv[1], o[nd][3] * inv[1]);
        *(__half2*)(att + tok0 + col) = h0;
        *(__half2*)(att + tok1 + col) = h1;
    }
}

// ---------------------------------------------------------------------------
// fp32 -> fp16 elementwise
// ---------------------------------------------------------------------------
__global__ __launch_bounds__(256) void convert_half_kernel(
    const float* __restrict__ x, __half* __restrict__ y, int n)
{
    int i = blockIdx.x * blockDim.x + threadIdx.x;
    if (i * 4 >= n) return;
    float4 v = ((const float4*)x)[i];
    __half2 h0 = __floats2half2_rn(v.x, v.y);
    __half2 h1 = __floats2half2_rn(v.z, v.w);
    ((__half2*)y)[2 * i]     = h0;
    ((__half2*)y)[2 * i + 1] = h1;
}

// ---------------------------------------------------------------------------
// W[K,N] fp32 -> transposed fp16 [N,K]
// ---------------------------------------------------------------------------
__global__ __launch_bounds__(256) void transpose_half_kernel(
    const float* __restrict__ W, __half* __restrict__ T, int K, int N)
{
    __shared__ float t[32][33];
    int n0 = blockIdx.x * 32, k0 = blockIdx.y * 32;
    int tx = threadIdx.x, ty = threadIdx.y;   // 32 x 8
#pragma unroll
    for (int i = 0; i < 32; i += 8)
        t[ty + i][tx] = W[(size_t)(k0 + ty + i) * N + n0 + tx];
    __syncthreads();
#pragma unroll
    for (int i = 0; i < 32; i += 8) {
        int nn = ty + i;
        T[(size_t)(n0 + nn) * K + k0 + tx] = __float2half_rn(t[tx][nn]);
    }
}

// ---------------------------------------------------------------------------
// kernel_launch
// ---------------------------------------------------------------------------
extern "C" void kernel_launch(void* const* d_in, const int* in_sizes, int n_in,
                              void* d_out, int out_size)
{
    const float* x      = (const float*)d_in[0];
    const float* w_qkv  = (const float*)d_in[1];
    const float* b_qkv  = (const float*)d_in[2];
    const float* w_proj = (const float*)d_in[3];
    const float* b_proj = (const float*)d_in[4];
    float* out = (float*)d_out;

    __half *qkvh, *xh, *atth, *wqh, *wph;
    cudaGetSymbolAddress((void**)&qkvh, g_qkvh);
    cudaGetSymbolAddress((void**)&xh,   g_xh);
    cudaGetSymbolAddress((void**)&atth, g_atth);
    cudaGetSymbolAddress((void**)&wqh,  g_wqkvh);
    cudaGetSymbolAddress((void**)&wph,  g_wprojh);

    static bool attr_done = false;
    if (!attr_done) {
        cudaFuncSetAttribute(gemm_f16_kernel<0>,
                             cudaFuncAttributeMaxDynamicSharedMemorySize, SMEM_BYTES);
        cudaFuncSetAttribute(gemm_f16_kernel<1>,
                             cudaFuncAttributeMaxDynamicSharedMemorySize, SMEM_BYTES);
        attr_done = true;
    }

    // 1) x -> fp16
    {
        int n = Mm * Cc;
        convert_half_kernel<<<(n / 4 + 255) / 256, 256>>>(x, xh, n);
    }
    // 2) transpose weights -> fp16
    transpose_half_kernel<<<dim3(3 * Cc / 32, Cc / 32), dim3(32, 8)>>>(w_qkv, wqh, Cc, 3 * Cc);
    transpose_half_kernel<<<dim3(Cc / 32, Cc / 32), dim3(32, 8)>>>(w_proj, wph, Cc, Cc);

    // 3) QKV GEMM -> fp16 qkv (q columns pre-scaled by 0.125*log2e)
    gemm_f16_kernel<1><<<dim3(3 * Cc / 128, Mm / 128), 128, SMEM_BYTES>>>(
        xh, wqh, b_qkv, nullptr, qkvh, 3 * Cc, Cc);

    // 4) tensor-core flash attention -> fp16
    attn_mma_kernel<<<dim3(Nn_ / 128, Bb * Hh), 256>>>(qkvh, atth);

    // 5) proj GEMM -> fp32 out
    gemm_f16_kernel<0><<<dim3(Cc / 128, Mm / 128), 128, SMEM_BYTES>>>(
        atth, wph, b_proj, out, nullptr, Cc, 0);
}

// round 8
// speedup vs baseline: 8.7650x; 1.0041x over previous
#include <cuda_runtime.h>
#include <cuda_fp16.h>
#include <cstdint>

#define Bb   8
#define Nn_  1024
#define Cc   1024
#define Hh   16
#define Mm   (Bb * Nn_)   // 8192
#define KK   1024

// q pre-scale: 1/sqrt(64) * log2(e), folded into QKV GEMM epilogue (q cols only)
#define ESCALE 0.18033688011112042f

// ---------------------------------------------------------------------------
// Device scratch
// ---------------------------------------------------------------------------
__device__ __align__(256) __half g_qkvh[(size_t)Mm * 3 * Cc];   // [8192,3072]
__device__ __align__(256) __half g_xh[(size_t)Mm * Cc];         // [8192,1024]
__device__ __align__(256) __half g_atth[(size_t)Mm * Cc];       // [8192,1024]
__device__ __align__(256) __half g_wqkvh[(size_t)3 * Cc * Cc];  // [3072,1024] transposed
__device__ __align__(256) __half g_wprojh[(size_t)Cc * Cc];     // [1024,1024] transposed

// ---------------------------------------------------------------------------
// helpers
// ---------------------------------------------------------------------------
__device__ __forceinline__ uint32_t smem_u32(const void* p) {
    uint32_t a;
    asm("{ .reg .u64 t; cvta.to.shared.u64 t, %1; cvt.u32.u64 %0, t; }" : "=r"(a) : "l"(p));
    return a;
}
__device__ __forceinline__ void mma_f16(float* d, const uint32_t* a,
                                        uint32_t b0, uint32_t b1) {
    asm volatile(
        "mma.sync.aligned.m16n8k16.row.col.f32.f16.f16.f32 "
        "{%0,%1,%2,%3}, {%4,%5,%6,%7}, {%8,%9}, {%0,%1,%2,%3};"
        : "+f"(d[0]), "+f"(d[1]), "+f"(d[2]), "+f"(d[3])
        : "r"(a[0]), "r"(a[1]), "r"(a[2]), "r"(a[3]), "r"(b0), "r"(b1));
}
#define LDSM4(r0, r1, r2, r3, addr)                                          \
    asm volatile("ldmatrix.sync.aligned.m8n8.x4.shared.b16 {%0,%1,%2,%3}, [%4];" \
                 : "=r"(r0), "=r"(r1), "=r"(r2), "=r"(r3) : "r"(addr))
#define LDSM4T(r0, r1, r2, r3, addr)                                         \
    asm volatile("ldmatrix.sync.aligned.m8n8.x4.trans.shared.b16 {%0,%1,%2,%3}, [%4];" \
                 : "=r"(r0), "=r"(r1), "=r"(r2), "=r"(r3) : "r"(addr))
__device__ __forceinline__ float ex2f(float x) {
    float r; asm("ex2.approx.f32 %0, %1;" : "=f"(r) : "f"(x)); return r;
}
__device__ __forceinline__ float rcpf(float x) {
    float r; asm("rcp.approx.f32 %0, %1;" : "=f"(r) : "f"(x)); return r;
}

// ---- 128B-row swizzle (8 x 16B segs per row) ----
__device__ __forceinline__ uint32_t swz128(int row, int seg) {
    return (uint32_t)((row << 7) + ((seg ^ (row & 7)) << 4));
}
__device__ __forceinline__ uint32_t ldsmA_q(uint32_t base, int r0, int kt, int lane) {
    int f = lane >> 3;
    return base + swz128(r0 + (lane & 7) + ((f & 1) << 3), (kt << 1) + (f >> 1));
}
__device__ __forceinline__ uint32_t ldsmB_k(uint32_t base, int nb, int kt, int lane) {
    int f = lane >> 3;
    return base + swz128(nb + (lane & 7) + ((f >> 1) << 3), (kt << 1) + (f & 1));
}
__device__ __forceinline__ uint32_t ldsmBT_v(uint32_t base, int kb, int ndb, int lane) {
    int f = lane >> 3;
    return base + swz128(kb + (lane & 7) + ((f & 1) << 3), (ndb << 1) + (f >> 1));
}

// ---------------------------------------------------------------------------
// fp16 tensor-core GEMM: C[M,Ntot] = A[M,K] @ B[Ntot,K]^T + bias
// 128x128 CTA tile, BK=64, 128 threads (4 warps, 64x64 warp tiles),
// 3-stage cp.async pipeline.
// ---------------------------------------------------------------------------
#define STAGE_BYTES 32768          // A(128x64) + B(128x64) fp16
#define SMEM_BYTES  (3 * STAGE_BYTES)
#define NCHUNK      (KK / 64)      // 16

__device__ __forceinline__ void load_chunk64(
    uint32_t stage, const __half* a, const __half* b, int kc, int tid)
{
    int koff = kc * 64;
    const __half* bases[2] = {a, b};
#pragma unroll
    for (int t = 0; t < 2; t++) {
        const __half* base = bases[t];
        uint32_t sdst = stage + t * 16384;
#pragma unroll
        for (int i = 0; i < 8; i++) {
            int idx = tid + (i << 7);        // 0..1023
            int r   = idx >> 3;              // 0..127
            int seg = idx & 7;               // 0..7
            const __half* src = base + (size_t)r * KK + koff + (seg << 3);
            uint32_t dst = sdst + swz128(r, seg);
            asm volatile("cp.async.cg.shared.global [%0], [%1], 16;"
                         :: "r"(dst), "l"(src));
        }
    }
}

template <int HALF_OUT>
__global__ __launch_bounds__(128)
void gemm_f16_kernel(const __half* __restrict__ A, const __half* __restrict__ B,
                     const float* __restrict__ bias, float* __restrict__ Cf,
                     __half* __restrict__ Ch, int Ntot, int scale_cols)
{
    extern __shared__ char smem[];
    uint32_t sb = smem_u32(smem);

    int tid  = threadIdx.x;
    int lane = tid & 31;
    int wid  = tid >> 5;
    int wm   = wid >> 1;     // 0..1
    int wn   = wid & 1;      // 0..1
    int row0 = blockIdx.y * 128;
    int col0 = blockIdx.x * 128;

    const __half* a = A + (size_t)row0 * KK;
    const __half* b = B + (size_t)col0 * KK;

    float acc[4][8][4];
#pragma unroll
    for (int mt = 0; mt < 4; mt++)
#pragma unroll
        for (int j = 0; j < 8; j++)
#pragma unroll
            for (int e = 0; e < 4; e++) acc[mt][j][e] = 0.0f;

    load_chunk64(sb, a, b, 0, tid);
    asm volatile("cp.async.commit_group;");
    load_chunk64(sb + STAGE_BYTES, a, b, 1, tid);
    asm volatile("cp.async.commit_group;");

    int st = 0;
    for (int c = 0; c < NCHUNK; c++) {
        if (c + 2 < NCHUNK) {
            int st2 = st + 2; if (st2 >= 3) st2 -= 3;
            load_chunk64(sb + (uint32_t)st2 * STAGE_BYTES, a, b, c + 2, tid);
            asm volatile("cp.async.commit_group;");
            asm volatile("cp.async.wait_group 2;");
        } else if (c + 1 < NCHUNK) {
            asm volatile("cp.async.wait_group 1;");
        } else {
            asm volatile("cp.async.wait_group 0;");
        }
        __syncthreads();

        uint32_t As = sb + (uint32_t)st * STAGE_BYTES;
        uint32_t Bs = As + 16384;

#pragma unroll
        for (int ks = 0; ks < 4; ks++) {
            uint32_t af[4][4];
#pragma unroll
            for (int mt = 0; mt < 4; mt++)
                LDSM4(af[mt][0], af[mt][1], af[mt][2], af[mt][3],
                      ldsmA_q(As, wm * 64 + mt * 16, ks, lane));
#pragma unroll
            for (int ntp = 0; ntp < 4; ntp++) {
                uint32_t bf[4];
                LDSM4(bf[0], bf[1], bf[2], bf[3],
                      ldsmB_k(Bs, wn * 64 + ntp * 16, ks, lane));
#pragma unroll
                for (int mt = 0; mt < 4; mt++) {
                    mma_f16(acc[mt][2 * ntp],     af[mt], bf[0], bf[1]);
                    mma_f16(acc[mt][2 * ntp + 1], af[mt], bf[2], bf[3]);
                }
            }
        }
        __syncthreads();
        if (++st == 3) st = 0;
    }

#pragma unroll
    for (int mt = 0; mt < 4; mt++) {
#pragma unroll
        for (int j = 0; j < 8; j++) {
            int grow = row0 + wm * 64 + mt * 16 + (lane >> 2);
            int gcol = col0 + wn * 64 + j * 8 + ((lane & 3) << 1);
            float2 bv = *(const float2*)(bias + gcol);
            float v0 = acc[mt][j][0] + bv.x;
            float v1 = acc[mt][j][1] + bv.y;
            float v2 = acc[mt][j][2] + bv.x;
            float v3 = acc[mt][j][3] + bv.y;
            if (HALF_OUT) {
                float s = (gcol < scale_cols) ? ESCALE : 1.0f;
                __half2 h0 = __floats2half2_rn(v0 * s, v1 * s);
                __half2 h1 = __floats2half2_rn(v2 * s, v3 * s);
                *(__half2*)(Ch + (size_t)grow * Ntot + gcol)       = h0;
                *(__half2*)(Ch + (size_t)(grow + 8) * Ntot + gcol) = h1;
            } else {
                *(float2*)(Cf + (size_t)grow * Ntot + gcol)       = make_float2(v0, v1);
                *(float2*)(Cf + (size_t)(grow + 8) * Ntot + gcol) = make_float2(v2, v3);
            }
        }
    }
}

// ---------------------------------------------------------------------------
// Tensor-core flash attention (fp16 in, fp32 softmax, fp16 out)
// grid = (8 q-tiles, 128 bh), block = 256 (8 warps, 16 q rows each)
// KV triple-buffered, conditional rescale.
// ---------------------------------------------------------------------------
__device__ __forceinline__ void attn_load_kv(
    uint32_t KS, uint32_t VS,
    const __half* kbase, const __half* vbase, int t, int tid)
{
    // 256 threads, 32x64 fp16 tile = 256 16B segs each for K and V
    int r = tid >> 3;
    int s = tid & 7;
    size_t goff = (size_t)(t * 32 + r) * 3072 + (s << 3);
    asm volatile("cp.async.cg.shared.global [%0], [%1], 16;"
                 :: "r"(KS + swz128(r, s)), "l"(kbase + goff));
    asm volatile("cp.async.cg.shared.global [%0], [%1], 16;"
                 :: "r"(VS + swz128(r, s)), "l"(vbase + goff));
}

__global__ __launch_bounds__(256)
void attn_mma_kernel(const __half* __restrict__ qkv, __half* __restrict__ att)
{
    __shared__ __align__(1024) char sm[40960];
    uint32_t sb = smem_u32(sm);
    const uint32_t QS = sb;                       // 16KB
    uint32_t KS[3] = {sb + 16384, sb + 20480, sb + 24576};
    uint32_t VS[3] = {sb + 28672, sb + 32768, sb + 36864};

    int tid  = threadIdx.x;
    int lane = tid & 31;
    int w    = tid >> 5;       // 0..7
    int qt   = blockIdx.x;
    int bh   = blockIdx.y;
    int b    = bh >> 4;
    int h    = bh & 15;

    const __half* qbase = qkv + ((size_t)(b * Nn_ + qt * 128)) * 3072 + h * 64;
    const __half* kbase = qkv + ((size_t)(b * Nn_)) * 3072 + 1024 + h * 64;
    const __half* vbase = kbase + 1024;

    // Q tile 128x64 = 1024 segs, 256 threads x 4
#pragma unroll
    for (int i = 0; i < 4; i++) {
        int idx = tid + (i << 8);
        int r = idx >> 3, s = idx & 7;
        asm volatile("cp.async.cg.shared.global [%0], [%1], 16;"
                     :: "r"(QS + swz128(r, s)), "l"(qbase + (size_t)r * 3072 + (s << 3)));
    }
    attn_load_kv(KS[0], VS[0], kbase, vbase, 0, tid);
    asm volatile("cp.async.commit_group;");
    attn_load_kv(KS[1], VS[1], kbase, vbase, 1, tid);
    asm volatile("cp.async.commit_group;");

    float o[8][4];
#pragma unroll
    for (int nd = 0; nd < 8; nd++)
#pragma unroll
        for (int e = 0; e < 4; e++) o[nd][e] = 0.0f;
    float mrow[2] = {-1e30f, -1e30f};
    float lrow[2] = {0.0f, 0.0f};
    uint32_t qf[4][4];

    int st = 0;
    for (int t = 0; t < 32; t++) {
        if (t + 2 < 32) {
            int st2 = st + 2; if (st2 >= 3) st2 -= 3;
            attn_load_kv(KS[st2], VS[st2], kbase, vbase, t + 2, tid);
            asm volatile("cp.async.commit_group;");
            asm volatile("cp.async.wait_group 2;");
        } else if (t + 1 < 32) {
            asm volatile("cp.async.wait_group 1;");
        } else {
            asm volatile("cp.async.wait_group 0;");
        }
        __syncthreads();

        if (t == 0) {
#pragma unroll
            for (int kt = 0; kt < 4; kt++)
                LDSM4(qf[kt][0], qf[kt][1], qf[kt][2], qf[kt][3],
                      ldsmA_q(QS, w * 16, kt, lane));
        }

        uint32_t Kt = KS[st];
        uint32_t Vt = VS[st];

        // S = Q K^T  (16 x 32 per warp)
        float s[4][4];
#pragma unroll
        for (int j = 0; j < 4; j++)
#pragma unroll
            for (int e = 0; e < 4; e++) s[j][e] = 0.0f;

#pragma unroll
        for (int kt = 0; kt < 4; kt++) {
#pragma unroll
            for (int nb = 0; nb < 2; nb++) {
                uint32_t bk[4];
                LDSM4(bk[0], bk[1], bk[2], bk[3], ldsmB_k(Kt, nb * 16, kt, lane));
                mma_f16(s[2 * nb],     qf[kt], bk[0], bk[1]);
                mma_f16(s[2 * nb + 1], qf[kt], bk[2], bk[3]);
            }
        }

        // online softmax (rows g = lane>>2 and g+8)
#pragma unroll
        for (int r = 0; r < 2; r++) {
            float mx = -1e30f;
#pragma unroll
            for (int j = 0; j < 4; j++)
                mx = fmaxf(mx, fmaxf(s[j][2 * r], s[j][2 * r + 1]));
            mx = fmaxf(mx, __shfl_xor_sync(0xFFFFFFFFu, mx, 1));
            mx = fmaxf(mx, __shfl_xor_sync(0xFFFFFFFFu, mx, 2));
            float mold = mrow[r];
            if (mx > mold) {                 // rescale only on max update
                mrow[r] = mx;
                float f = ex2f(mold - mx);
                lrow[r] *= f;
#pragma unroll
                for (int nd = 0; nd < 8; nd++) {
                    o[nd][2 * r]     *= f;
                    o[nd][2 * r + 1] *= f;
                }
            }
            float mn = mrow[r];
            float ls = 0.0f;
#pragma unroll
            for (int j = 0; j < 4; j++) {
                float p0 = ex2f(s[j][2 * r]     - mn);
                float p1 = ex2f(s[j][2 * r + 1] - mn);
                s[j][2 * r]     = p0;
                s[j][2 * r + 1] = p1;
                ls += p0 + p1;
            }
            lrow[r] += ls;
        }

        // pack P -> fp16 A-frags; O += P V
        uint32_t pa[2][4];
#pragma unroll
        for (int kt = 0; kt < 2; kt++) {
            int j0 = 2 * kt, j1 = 2 * kt + 1;
            __half2 h0 = __floats2half2_rn(s[j0][0], s[j0][1]);
            __half2 h1 = __floats2half2_rn(s[j0][2], s[j0][3]);
            __half2 h2 = __floats2half2_rn(s[j1][0], s[j1][1]);
            __half2 h3 = __floats2half2_rn(s[j1][2], s[j1][3]);
            pa[kt][0] = *(uint32_t*)&h0;
            pa[kt][1] = *(uint32_t*)&h1;
            pa[kt][2] = *(uint32_t*)&h2;
            pa[kt][3] = *(uint32_t*)&h3;
        }
#pragma unroll
        for (int kt = 0; kt < 2; kt++) {
#pragma unroll
            for (int ndb = 0; ndb < 4; ndb++) {
                uint32_t bv[4];
                LDSM4T(bv[0], bv[1], bv[2], bv[3], ldsmBT_v(Vt, kt * 16, ndb, lane));
                mma_f16(o[2 * ndb],     pa[kt], bv[0], bv[1]);
                mma_f16(o[2 * ndb + 1], pa[kt], bv[2], bv[3]);
            }
        }
        __syncthreads();
        if (++st == 3) st = 0;
    }

    float inv[2];
#pragma unroll
    for (int r = 0; r < 2; r++) {
        float lv = lrow[r];
        lv += __shfl_xor_sync(0xFFFFFFFFu, lv, 1);
        lv += __shfl_xor_sync(0xFFFFFFFFu, lv, 2);
        inv[r] = rcpf(lv);
    }

    int g   = lane >> 2;
    int tig = lane & 3;
    int row = qt * 128 + w * 16 + g;
    size_t tok0 = ((size_t)(b * Nn_ + row)) * Cc + h * 64;
    size_t tok1 = ((size_t)(b * Nn_ + row + 8)) * Cc + h * 64;
#pragma unroll
    for (int nd = 0; nd < 8; nd++) {
        int col = nd * 8 + tig * 2;
        __half2 h0 = __floats2half2_rn(o[nd][0] * inv[0], o[nd][1] * inv[0]);
        __half2 h1 = __floats2half2_rn(o[nd][2] * inv[1], o[nd][3] * inv[1]);
        *(__half2*)(att + tok0 + col) = h0;
        *(__half2*)(att + tok1 + col) = h1;
    }
}

// ---------------------------------------------------------------------------
// fp32 -> fp16 elementwise
// ---------------------------------------------------------------------------
__global__ __launch_bounds__(256) void convert_half_kernel(
    const float* __restrict__ x, __half* __restrict__ y, int n)
{
    int i = blockIdx.x * blockDim.x + threadIdx.x;
    if (i * 4 >= n) return;
    float4 v = ((const float4*)x)[i];
    __half2 h0 = __floats2half2_rn(v.x, v.y);
    __half2 h1 = __floats2half2_rn(v.z, v.w);
    ((__half2*)y)[2 * i]     = h0;
    ((__half2*)y)[2 * i + 1] = h1;
}

// ---------------------------------------------------------------------------
// W[K,N] fp32 -> transposed fp16 [N,K]
// ---------------------------------------------------------------------------
__global__ __launch_bounds__(256) void transpose_half_kernel(
    const float* __restrict__ W, __half* __restrict__ T, int K, int N)
{
    __shared__ float t[32][33];
    int n0 = blockIdx.x * 32, k0 = blockIdx.y * 32;
    int tx = threadIdx.x, ty = threadIdx.y;   // 32 x 8
#pragma unroll
    for (int i = 0; i < 32; i += 8)
        t[ty + i][tx] = W[(size_t)(k0 + ty + i) * N + n0 + tx];
    __syncthreads();
#pragma unroll
    for (int i = 0; i < 32; i += 8) {
        int nn = ty + i;
        T[(size_t)(n0 + nn) * K + k0 + tx] = __float2half_rn(t[tx][nn]);
    }
}

// ---------------------------------------------------------------------------
// kernel_launch
// ---------------------------------------------------------------------------
extern "C" void kernel_launch(void* const* d_in, const int* in_sizes, int n_in,
                              void* d_out, int out_size)
{
    const float* x      = (const float*)d_in[0];
    const float* w_qkv  = (const float*)d_in[1];
    const float* b_qkv  = (const float*)d_in[2];
    const float* w_proj = (const float*)d_in[3];
    const float* b_proj = (const float*)d_in[4];
    float* out = (float*)d_out;

    __half *qkvh, *xh, *atth, *wqh, *wph;
    cudaGetSymbolAddress((void**)&qkvh, g_qkvh);
    cudaGetSymbolAddress((void**)&xh,   g_xh);
    cudaGetSymbolAddress((void**)&atth, g_atth);
    cudaGetSymbolAddress((void**)&wqh,  g_wqkvh);
    cudaGetSymbolAddress((void**)&wph,  g_wprojh);

    static bool attr_done = false;
    if (!attr_done) {
        cudaFuncSetAttribute(gemm_f16_kernel<0>,
                             cudaFuncAttributeMaxDynamicSharedMemorySize, SMEM_BYTES);
        cudaFuncSetAttribute(gemm_f16_kernel<1>,
                             cudaFuncAttributeMaxDynamicSharedMemorySize, SMEM_BYTES);
        attr_done = true;
    }

    // 1) x -> fp16
    {
        int n = Mm * Cc;
        convert_half_kernel<<<(n / 4 + 255) / 256, 256>>>(x, xh, n);
    }
    // 2) transpose weights -> fp16
    transpose_half_kernel<<<dim3(3 * Cc / 32, Cc / 32), dim3(32, 8)>>>(w_qkv, wqh, Cc, 3 * Cc);
    transpose_half_kernel<<<dim3(Cc / 32, Cc / 32), dim3(32, 8)>>>(w_proj, wph, Cc, Cc);

    // 3) QKV GEMM -> fp16 qkv (q columns pre-scaled by 0.125*log2e)
    gemm_f16_kernel<1><<<dim3(3 * Cc / 128, Mm / 128), 128, SMEM_BYTES>>>(
        xh, wqh, b_qkv, nullptr, qkvh, 3 * Cc, Cc);

    // 4) tensor-core flash attention -> fp16
    attn_mma_kernel<<<dim3(Nn_ / 128, Bb * Hh), 256>>>(qkvh, atth);

    // 5) proj GEMM -> fp32 out
    gemm_f16_kernel<0><<<dim3(Cc / 128, Mm / 128), 128, SMEM_BYTES>>>(
        atth, wph, b_proj, out, nullptr, Cc, 0);
}

// round 9
// speedup vs baseline: 9.2493x; 1.0553x over previous
#include <cuda_runtime.h>
#include <cuda_fp16.h>
#include <cstdint>

#define Bb   8
#define Nn_  1024
#define Cc   1024
#define Hh   16
#define Mm   (Bb * Nn_)   // 8192
#define KK   1024

// q pre-scale: 1/sqrt(64) * log2(e), folded into QKV GEMM epilogue (q cols only)
#define ESCALE 0.18033688011112042f

// ---------------------------------------------------------------------------
// Device scratch
// ---------------------------------------------------------------------------
__device__ __align__(256) __half g_qkvh[(size_t)Mm * 3 * Cc];   // [8192,3072]
__device__ __align__(256) __half g_xh[(size_t)Mm * Cc];         // [8192,1024]
__device__ __align__(256) __half g_atth[(size_t)Mm * Cc];       // [8192,1024]
__device__ __align__(256) __half g_wqkvh[(size_t)3 * Cc * Cc];  // [3072,1024] transposed
__device__ __align__(256) __half g_wprojh[(size_t)Cc * Cc];     // [1024,1024] transposed

// ---------------------------------------------------------------------------
// helpers
// ---------------------------------------------------------------------------
__device__ __forceinline__ uint32_t smem_u32(const void* p) {
    uint32_t a;
    asm("{ .reg .u64 t; cvta.to.shared.u64 t, %1; cvt.u32.u64 %0, t; }" : "=r"(a) : "l"(p));
    return a;
}
__device__ __forceinline__ void mma_f16(float* d, const uint32_t* a,
                                        uint32_t b0, uint32_t b1) {
    asm volatile(
        "mma.sync.aligned.m16n8k16.row.col.f32.f16.f16.f32 "
        "{%0,%1,%2,%3}, {%4,%5,%6,%7}, {%8,%9}, {%0,%1,%2,%3};"
        : "+f"(d[0]), "+f"(d[1]), "+f"(d[2]), "+f"(d[3])
        : "r"(a[0]), "r"(a[1]), "r"(a[2]), "r"(a[3]), "r"(b0), "r"(b1));
}
#define LDSM4(r0, r1, r2, r3, addr)                                          \
    asm volatile("ldmatrix.sync.aligned.m8n8.x4.shared.b16 {%0,%1,%2,%3}, [%4];" \
                 : "=r"(r0), "=r"(r1), "=r"(r2), "=r"(r3) : "r"(addr))
#define LDSM4T(r0, r1, r2, r3, addr)                                         \
    asm volatile("ldmatrix.sync.aligned.m8n8.x4.trans.shared.b16 {%0,%1,%2,%3}, [%4];" \
                 : "=r"(r0), "=r"(r1), "=r"(r2), "=r"(r3) : "r"(addr))
__device__ __forceinline__ float ex2f(float x) {
    float r; asm("ex2.approx.f32 %0, %1;" : "=f"(r) : "f"(x)); return r;
}
__device__ __forceinline__ float rcpf(float x) {
    float r; asm("rcp.approx.f32 %0, %1;" : "=f"(r) : "f"(x)); return r;
}

// ---- 128B-row swizzle (8 x 16B segs per row) ----
__device__ __forceinline__ uint32_t swz128(int row, int seg) {
    return (uint32_t)((row << 7) + ((seg ^ (row & 7)) << 4));
}
__device__ __forceinline__ uint32_t ldsmA_q(uint32_t base, int r0, int kt, int lane) {
    int f = lane >> 3;
    return base + swz128(r0 + (lane & 7) + ((f & 1) << 3), (kt << 1) + (f >> 1));
}
__device__ __forceinline__ uint32_t ldsmB_k(uint32_t base, int nb, int kt, int lane) {
    int f = lane >> 3;
    return base + swz128(nb + (lane & 7) + ((f >> 1) << 3), (kt << 1) + (f & 1));
}
__device__ __forceinline__ uint32_t ldsmBT_v(uint32_t base, int kb, int ndb, int lane) {
    int f = lane >> 3;
    return base + swz128(kb + (lane & 7) + ((f & 1) << 3), (ndb << 1) + (f >> 1));
}

// ---------------------------------------------------------------------------
// fp16 tensor-core GEMM: C[M,Ntot] = A[M,K] @ B[Ntot,K]^T + bias
// 128x128 CTA tile, BK=64, 128 threads (4 warps, 64x64 warp tiles),
// 3-stage cp.async pipeline, ONE barrier per chunk.
// ---------------------------------------------------------------------------
#define STAGE_BYTES 32768          // A(128x64) + B(128x64) fp16
#define SMEM_BYTES  (3 * STAGE_BYTES)
#define NCHUNK      (KK / 64)      // 16

__device__ __forceinline__ void load_chunk64(
    uint32_t stage, const __half* a, const __half* b, int kc, int tid)
{
    int koff = kc * 64;
    const __half* bases[2] = {a, b};
#pragma unroll
    for (int t = 0; t < 2; t++) {
        const __half* base = bases[t];
        uint32_t sdst = stage + t * 16384;
#pragma unroll
        for (int i = 0; i < 8; i++) {
            int idx = tid + (i << 7);        // 0..1023
            int r   = idx >> 3;              // 0..127
            int seg = idx & 7;               // 0..7
            const __half* src = base + (size_t)r * KK + koff + (seg << 3);
            uint32_t dst = sdst + swz128(r, seg);
            asm volatile("cp.async.cg.shared.global [%0], [%1], 16;"
                         :: "r"(dst), "l"(src));
        }
    }
}

template <int HALF_OUT>
__global__ __launch_bounds__(128)
void gemm_f16_kernel(const __half* __restrict__ A, const __half* __restrict__ B,
                     const float* __restrict__ bias, float* __restrict__ Cf,
                     __half* __restrict__ Ch, int Ntot, int scale_cols)
{
    extern __shared__ char smem[];
    uint32_t sb = smem_u32(smem);

    int tid  = threadIdx.x;
    int lane = tid & 31;
    int wid  = tid >> 5;
    int wm   = wid >> 1;     // 0..1
    int wn   = wid & 1;      // 0..1
    int row0 = blockIdx.y * 128;
    int col0 = blockIdx.x * 128;

    const __half* a = A + (size_t)row0 * KK;
    const __half* b = B + (size_t)col0 * KK;

    float acc[4][8][4];
#pragma unroll
    for (int mt = 0; mt < 4; mt++)
#pragma unroll
        for (int j = 0; j < 8; j++)
#pragma unroll
            for (int e = 0; e < 4; e++) acc[mt][j][e] = 0.0f;

    load_chunk64(sb, a, b, 0, tid);
    asm volatile("cp.async.commit_group;");
    load_chunk64(sb + STAGE_BYTES, a, b, 1, tid);
    asm volatile("cp.async.commit_group;");

    int st = 0;
    for (int c = 0; c < NCHUNK; c++) {
        if (c + 1 < NCHUNK) {
            asm volatile("cp.async.wait_group 1;");   // chunk c resident
        } else {
            asm volatile("cp.async.wait_group 0;");
        }
        __syncthreads();   // also proves all threads finished reading stage (st+2)%3

        if (c + 2 < NCHUNK) {
            int st2 = st + 2; if (st2 >= 3) st2 -= 3;
            load_chunk64(sb + (uint32_t)st2 * STAGE_BYTES, a, b, c + 2, tid);
            asm volatile("cp.async.commit_group;");
        }

        uint32_t As = sb + (uint32_t)st * STAGE_BYTES;
        uint32_t Bs = As + 16384;

#pragma unroll
        for (int ks = 0; ks < 4; ks++) {
            uint32_t af[4][4];
#pragma unroll
            for (int mt = 0; mt < 4; mt++)
                LDSM4(af[mt][0], af[mt][1], af[mt][2], af[mt][3],
                      ldsmA_q(As, wm * 64 + mt * 16, ks, lane));
#pragma unroll
            for (int ntp = 0; ntp < 4; ntp++) {
                uint32_t bf[4];
                LDSM4(bf[0], bf[1], bf[2], bf[3],
                      ldsmB_k(Bs, wn * 64 + ntp * 16, ks, lane));
#pragma unroll
                for (int mt = 0; mt < 4; mt++) {
                    mma_f16(acc[mt][2 * ntp],     af[mt], bf[0], bf[1]);
                    mma_f16(acc[mt][2 * ntp + 1], af[mt], bf[2], bf[3]);
                }
            }
        }
        if (++st == 3) st = 0;
    }

#pragma unroll
    for (int mt = 0; mt < 4; mt++) {
#pragma unroll
        for (int j = 0; j < 8; j++) {
            int grow = row0 + wm * 64 + mt * 16 + (lane >> 2);
            int gcol = col0 + wn * 64 + j * 8 + ((lane & 3) << 1);
            float2 bv = *(const float2*)(bias + gcol);
            float v0 = acc[mt][j][0] + bv.x;
            float v1 = acc[mt][j][1] + bv.y;
            float v2 = acc[mt][j][2] + bv.x;
            float v3 = acc[mt][j][3] + bv.y;
            if (HALF_OUT) {
                float s = (gcol < scale_cols) ? ESCALE : 1.0f;
                __half2 h0 = __floats2half2_rn(v0 * s, v1 * s);
                __half2 h1 = __floats2half2_rn(v2 * s, v3 * s);
                *(__half2*)(Ch + (size_t)grow * Ntot + gcol)       = h0;
                *(__half2*)(Ch + (size_t)(grow + 8) * Ntot + gcol) = h1;
            } else {
                *(float2*)(Cf + (size_t)grow * Ntot + gcol)       = make_float2(v0, v1);
                *(float2*)(Cf + (size_t)(grow + 8) * Ntot + gcol) = make_float2(v2, v3);
            }
        }
    }
}

// ---------------------------------------------------------------------------
// Tensor-core flash attention (fp16 in, fp32 softmax, fp16 out)
// grid = (8 q-tiles, 128 bh), block = 256 (8 warps, 16 q rows each)
// 64-key KV tiles, 3-stage pipeline, ONE barrier per tile.
// ---------------------------------------------------------------------------
__device__ __forceinline__ void attn_load_kv64(
    uint32_t KS, uint32_t VS,
    const __half* kbase, const __half* vbase, int t, int tid)
{
    // 64x64 fp16 tile = 512 16B segs; 256 threads x 2 each for K and V
#pragma unroll
    for (int i = 0; i < 2; i++) {
        int idx = tid + (i << 8);
        int r   = idx >> 3;              // 0..63
        int s   = idx & 7;
        size_t goff = (size_t)(t * 64 + r) * 3072 + (s << 3);
        asm volatile("cp.async.cg.shared.global [%0], [%1], 16;"
                     :: "r"(KS + swz128(r, s)), "l"(kbase + goff));
        asm volatile("cp.async.cg.shared.global [%0], [%1], 16;"
                     :: "r"(VS + swz128(r, s)), "l"(vbase + goff));
    }
}

#define NTILE 16   // 1024 / 64

__global__ __launch_bounds__(256)
void attn_mma_kernel(const __half* __restrict__ qkv, __half* __restrict__ att)
{
    __shared__ __align__(1024) char sm[65536];
    uint32_t sb = smem_u32(sm);
    const uint32_t QS = sb;                       // 16KB
    uint32_t KS[3] = {sb + 16384, sb + 32768, sb + 49152};          // 8KB each
    uint32_t VS[3] = {sb + 16384 + 8192, sb + 32768 + 8192, sb + 49152 + 8192};

    int tid  = threadIdx.x;
    int lane = tid & 31;
    int w    = tid >> 5;       // 0..7
    int qt   = blockIdx.x;
    int bh   = blockIdx.y;
    int b    = bh >> 4;
    int h    = bh & 15;

    const __half* qbase = qkv + ((size_t)(b * Nn_ + qt * 128)) * 3072 + h * 64;
    const __half* kbase = qkv + ((size_t)(b * Nn_)) * 3072 + 1024 + h * 64;
    const __half* vbase = kbase + 1024;

    // Q tile 128x64 = 1024 segs, 256 threads x 4
#pragma unroll
    for (int i = 0; i < 4; i++) {
        int idx = tid + (i << 8);
        int r = idx >> 3, s = idx & 7;
        asm volatile("cp.async.cg.shared.global [%0], [%1], 16;"
                     :: "r"(QS + swz128(r, s)), "l"(qbase + (size_t)r * 3072 + (s << 3)));
    }
    attn_load_kv64(KS[0], VS[0], kbase, vbase, 0, tid);
    asm volatile("cp.async.commit_group;");
    attn_load_kv64(KS[1], VS[1], kbase, vbase, 1, tid);
    asm volatile("cp.async.commit_group;");

    float o[8][4];
#pragma unroll
    for (int nd = 0; nd < 8; nd++)
#pragma unroll
        for (int e = 0; e < 4; e++) o[nd][e] = 0.0f;
    float mrow[2] = {-1e30f, -1e30f};
    float lrow[2] = {0.0f, 0.0f};
    uint32_t qf[4][4];

    int st = 0;
    for (int t = 0; t < NTILE; t++) {
        if (t + 1 < NTILE) {
            asm volatile("cp.async.wait_group 1;");
        } else {
            asm volatile("cp.async.wait_group 0;");
        }
        __syncthreads();

        if (t + 2 < NTILE) {
            int st2 = st + 2; if (st2 >= 3) st2 -= 3;
            attn_load_kv64(KS[st2], VS[st2], kbase, vbase, t + 2, tid);
            asm volatile("cp.async.commit_group;");
        }

        if (t == 0) {
#pragma unroll
            for (int kt = 0; kt < 4; kt++)
                LDSM4(qf[kt][0], qf[kt][1], qf[kt][2], qf[kt][3],
                      ldsmA_q(QS, w * 16, kt, lane));
        }

        uint32_t Kt = KS[st];
        uint32_t Vt = VS[st];

        // S = Q K^T  (16 x 64 per warp)
        float s[8][4];
#pragma unroll
        for (int j = 0; j < 8; j++)
#pragma unroll
            for (int e = 0; e < 4; e++) s[j][e] = 0.0f;

#pragma unroll
        for (int kt = 0; kt < 4; kt++) {
#pragma unroll
            for (int nb = 0; nb < 4; nb++) {
                uint32_t bk[4];
                LDSM4(bk[0], bk[1], bk[2], bk[3], ldsmB_k(Kt, nb * 16, kt, lane));
                mma_f16(s[2 * nb],     qf[kt], bk[0], bk[1]);
                mma_f16(s[2 * nb + 1], qf[kt], bk[2], bk[3]);
            }
        }

        // online softmax (rows g = lane>>2 and g+8)
#pragma unroll
        for (int r = 0; r < 2; r++) {
            float mx = -1e30f;
#pragma unroll
            for (int j = 0; j < 8; j++)
                mx = fmaxf(mx, fmaxf(s[j][2 * r], s[j][2 * r + 1]));
            mx = fmaxf(mx, __shfl_xor_sync(0xFFFFFFFFu, mx, 1));
            mx = fmaxf(mx, __shfl_xor_sync(0xFFFFFFFFu, mx, 2));
            float mold = mrow[r];
            if (mx > mold) {                 // rescale only on max update
                mrow[r] = mx;
                float f = ex2f(mold - mx);
                lrow[r] *= f;
#pragma unroll
                for (int nd = 0; nd < 8; nd++) {
                    o[nd][2 * r]     *= f;
                    o[nd][2 * r + 1] *= f;
                }
            }
            float mn = mrow[r];
            float ls = 0.0f;
#pragma unroll
            for (int j = 0; j < 8; j++) {
                float p0 = ex2f(s[j][2 * r]     - mn);
                float p1 = ex2f(s[j][2 * r + 1] - mn);
                s[j][2 * r]     = p0;
                s[j][2 * r + 1] = p1;
                ls += p0 + p1;
            }
            lrow[r] += ls;
        }

        // pack P -> fp16 A-frags (4 k-groups of 16 keys); O += P V
        uint32_t pa[4][4];
#pragma unroll
        for (int kt = 0; kt < 4; kt++) {
            int j0 = 2 * kt, j1 = 2 * kt + 1;
            __half2 h0 = __floats2half2_rn(s[j0][0], s[j0][1]);
            __half2 h1 = __floats2half2_rn(s[j0][2], s[j0][3]);
            __half2 h2 = __floats2half2_rn(s[j1][0], s[j1][1]);
            __half2 h3 = __floats2half2_rn(s[j1][2], s[j1][3]);
            pa[kt][0] = *(uint32_t*)&h0;
            pa[kt][1] = *(uint32_t*)&h1;
            pa[kt][2] = *(uint32_t*)&h2;
            pa[kt][3] = *(uint32_t*)&h3;
        }
#pragma unroll
        for (int kt = 0; kt < 4; kt++) {
#pragma unroll
            for (int ndb = 0; ndb < 4; ndb++) {
                uint32_t bv[4];
                LDSM4T(bv[0], bv[1], bv[2], bv[3], ldsmBT_v(Vt, kt * 16, ndb, lane));
                mma_f16(o[2 * ndb],     pa[kt], bv[0], bv[1]);
                mma_f16(o[2 * ndb + 1], pa[kt], bv[2], bv[3]);
            }
        }
        if (++st == 3) st = 0;
    }

    float inv[2];
#pragma unroll
    for (int r = 0; r < 2; r++) {
        float lv = lrow[r];
        lv += __shfl_xor_sync(0xFFFFFFFFu, lv, 1);
        lv += __shfl_xor_sync(0xFFFFFFFFu, lv, 2);
        inv[r] = rcpf(lv);
    }

    int g   = lane >> 2;
    int tig = lane & 3;
    int row = qt * 128 + w * 16 + g;
    size_t tok0 = ((size_t)(b * Nn_ + row)) * Cc + h * 64;
    size_t tok1 = ((size_t)(b * Nn_ + row + 8)) * Cc + h * 64;
#pragma unroll
    for (int nd = 0; nd < 8; nd++) {
        int col = nd * 8 + tig * 2;
        __half2 h0 = __floats2half2_rn(o[nd][0] * inv[0], o[nd][1] * inv[0]);
        __half2 h1 = __floats2half2_rn(o[nd][2] * inv[1], o[nd][3] * inv[1]);
        *(__half2*)(att + tok0 + col) = h0;
        *(__half2*)(att + tok1 + col) = h1;
    }
}

// ---------------------------------------------------------------------------
// fp32 -> fp16 elementwise
// ---------------------------------------------------------------------------
__global__ __launch_bounds__(256) void convert_half_kernel(
    const float* __restrict__ x, __half* __restrict__ y, int n)
{
    int i = blockIdx.x * blockDim.x + threadIdx.x;
    if (i * 4 >= n) return;
    float4 v = ((const float4*)x)[i];
    __half2 h0 = __floats2half2_rn(v.x, v.y);
    __half2 h1 = __floats2half2_rn(v.z, v.w);
    ((__half2*)y)[2 * i]     = h0;
    ((__half2*)y)[2 * i + 1] = h1;
}

// ---------------------------------------------------------------------------
// W[K,N] fp32 -> transposed fp16 [N,K]
// ---------------------------------------------------------------------------
__global__ __launch_bounds__(256) void transpose_half_kernel(
    const float* __restrict__ W, __half* __restrict__ T, int K, int N)
{
    __shared__ float t[32][33];
    int n0 = blockIdx.x * 32, k0 = blockIdx.y * 32;
    int tx = threadIdx.x, ty = threadIdx.y;   // 32 x 8
#pragma unroll
    for (int i = 0; i < 32; i += 8)
        t[ty + i][tx] = W[(size_t)(k0 + ty + i) * N + n0 + tx];
    __syncthreads();
#pragma unroll
    for (int i = 0; i < 32; i += 8) {
        int nn = ty + i;
        T[(size_t)(n0 + nn) * K + k0 + tx] = __float2half_rn(t[tx][nn]);
    }
}

// ---------------------------------------------------------------------------
// kernel_launch
// ---------------------------------------------------------------------------
extern "C" void kernel_launch(void* const* d_in, const int* in_sizes, int n_in,
                              void* d_out, int out_size)
{
    const float* x      = (const float*)d_in[0];
    const float* w_qkv  = (const float*)d_in[1];
    const float* b_qkv  = (const float*)d_in[2];
    const float* w_proj = (const float*)d_in[3];
    const float* b_proj = (const float*)d_in[4];
    float* out = (float*)d_out;

    __half *qkvh, *xh, *atth, *wqh, *wph;
    cudaGetSymbolAddress((void**)&qkvh, g_qkvh);
    cudaGetSymbolAddress((void**)&xh,   g_xh);
    cudaGetSymbolAddress((void**)&atth, g_atth);
    cudaGetSymbolAddress((void**)&wqh,  g_wqkvh);
    cudaGetSymbolAddress((void**)&wph,  g_wprojh);

    static bool attr_done = false;
    if (!attr_done) {
        cudaFuncSetAttribute(gemm_f16_kernel<0>,
                             cudaFuncAttributeMaxDynamicSharedMemorySize, SMEM_BYTES);
        cudaFuncSetAttribute(gemm_f16_kernel<1>,
                             cudaFuncAttributeMaxDynamicSharedMemorySize, SMEM_BYTES);
        attr_done = true;
    }

    // 1) x -> fp16
    {
        int n = Mm * Cc;
        convert_half_kernel<<<(n / 4 + 255) / 256, 256>>>(x, xh, n);
    }
    // 2) transpose weights -> fp16
    transpose_half_kernel<<<dim3(3 * Cc / 32, Cc / 32), dim3(32, 8)>>>(w_qkv, wqh, Cc, 3 * Cc);
    transpose_half_kernel<<<dim3(Cc / 32, Cc / 32), dim3(32, 8)>>>(w_proj, wph, Cc, Cc);

    // 3) QKV GEMM -> fp16 qkv (q columns pre-scaled by 0.125*log2e)
    gemm_f16_kernel<1><<<dim3(3 * Cc / 128, Mm / 128), 128, SMEM_BYTES>>>(
        xh, wqh, b_qkv, nullptr, qkvh, 3 * Cc, Cc);

    // 4) tensor-core flash attention -> fp16
    attn_mma_kernel<<<dim3(Nn_ / 128, Bb * Hh), 256>>>(qkvh, atth);

    // 5) proj GEMM -> fp32 out
    gemm_f16_kernel<0><<<dim3(Cc / 128, Mm / 128), 128, SMEM_BYTES>>>(
        atth, wph, b_proj, out, nullptr, Cc, 0);
}